// round 1
// baseline (speedup 1.0000x reference)
#include <cuda_runtime.h>
#include <math.h>

#define D_MODEL   256
#define N_LAYERS  6
#define N_HEADS   8
#define D_FF      1024
#define HEAD_DIM  32
#define BATCH     4
#define SEQ       2048
#define NTOK      (BATCH * SEQ)   // 8192

// ---------------------------------------------------------------------------
// Scratch (static __device__ arrays: allocation-free, allowed by harness)
// ---------------------------------------------------------------------------
__device__ float g_normed[NTOK * D_MODEL];
__device__ float g_q[NTOK * D_MODEL];
__device__ float g_k[NTOK * D_MODEL];
__device__ float g_v[NTOK * D_MODEL];
__device__ float g_attn[NTOK * D_MODEL];
__device__ float g_ffh[NTOK * D_FF];

// ---------------------------------------------------------------------------
// LayerNorm: one block (256 threads) per row of 256 elements
// ---------------------------------------------------------------------------
__global__ void __launch_bounds__(256) ln_kernel(
    const float* __restrict__ X, const float* __restrict__ S,
    const float* __restrict__ Bb, float* __restrict__ Y)
{
    const int row = blockIdx.x;
    const int tid = threadIdx.x;
    const float v = X[row * D_MODEL + tid];

    __shared__ float red[16];
    float s1 = v, s2 = v * v;
    #pragma unroll
    for (int off = 16; off > 0; off >>= 1) {
        s1 += __shfl_xor_sync(0xffffffffu, s1, off);
        s2 += __shfl_xor_sync(0xffffffffu, s2, off);
    }
    const int w = tid >> 5;
    if ((tid & 31) == 0) { red[w] = s1; red[8 + w] = s2; }
    __syncthreads();
    float sum = 0.f, sq = 0.f;
    #pragma unroll
    for (int i = 0; i < 8; i++) { sum += red[i]; sq += red[8 + i]; }
    const float mu  = sum * (1.0f / D_MODEL);
    const float var = sq * (1.0f / D_MODEL) - mu * mu;
    const float inv = rsqrtf(var + 1e-5f);
    Y[row * D_MODEL + tid] = (v - mu) * inv * S[tid] + Bb[tid];
}

// ---------------------------------------------------------------------------
// Tiled fp32 GEMM: C[rows,M] = A[rows,K] @ W[K,M] + bias (+GELU) (+residual)
// BM=BN=64, BK=16, 256 threads, 4x4 register tiles.
// ---------------------------------------------------------------------------
template <bool GELU, bool RES>
__global__ void __launch_bounds__(256) gemm_kernel(
    const float* __restrict__ A, const float* __restrict__ W,
    const float* __restrict__ bias, float* __restrict__ C,
    int K, int M)
{
    __shared__ float As[16][68];   // [k][m], padded
    __shared__ float Ws[16][68];   // [k][n], padded

    const int tid  = threadIdx.x;
    const int tx   = tid & 15;
    const int ty   = tid >> 4;
    const int row0 = blockIdx.y * 64;
    const int col0 = blockIdx.x * 64;

    float acc[4][4] = {};

    for (int k0 = 0; k0 < K; k0 += 16) {
        #pragma unroll
        for (int i = 0; i < 4; i++) {
            int idx = tid + i * 256;              // 0..1023
            int r = idx >> 4, c = idx & 15;       // A tile 64x16
            As[c][r] = A[(row0 + r) * K + k0 + c];
        }
        #pragma unroll
        for (int i = 0; i < 4; i++) {
            int idx = tid + i * 256;
            int r = idx >> 6, c = idx & 63;       // W tile 16x64
            Ws[r][c] = W[(k0 + r) * M + col0 + c];
        }
        __syncthreads();

        #pragma unroll
        for (int k = 0; k < 16; k++) {
            const float4 a4 = *reinterpret_cast<const float4*>(&As[k][ty * 4]);
            const float4 w4 = *reinterpret_cast<const float4*>(&Ws[k][tx * 4]);
            const float a[4] = {a4.x, a4.y, a4.z, a4.w};
            const float w[4] = {w4.x, w4.y, w4.z, w4.w};
            #pragma unroll
            for (int i = 0; i < 4; i++)
                #pragma unroll
                for (int j = 0; j < 4; j++)
                    acc[i][j] += a[i] * w[j];
        }
        __syncthreads();
    }

    #pragma unroll
    for (int i = 0; i < 4; i++) {
        const int row = row0 + ty * 4 + i;
        #pragma unroll
        for (int j = 0; j < 4; j++) {
            const int col = col0 + tx * 4 + j;
            float v = acc[i][j] + bias[col];
            if (GELU) v = 0.5f * v * (1.0f + erff(v * 0.70710678118654752f));
            if (RES)  v += C[row * M + col];
            C[row * M + col] = v;
        }
    }
}

// ---------------------------------------------------------------------------
// Flash attention (fp32): per block: one (b, h), 64 queries; loop key tiles of
// 64. 256 threads as 16x16; thread (ty,tx) owns 4 queries x (4 keys | 2 dims).
// ---------------------------------------------------------------------------
__global__ void __launch_bounds__(256) attn_kernel(
    const float* __restrict__ Q, const float* __restrict__ K,
    const float* __restrict__ V, float* __restrict__ O)
{
    __shared__ float Qs[64][33];
    __shared__ float Ks[64][33];
    __shared__ float Vs[64][34];   // even pitch for float2 reads
    __shared__ float Ps[64][68];

    const int tid = threadIdx.x;
    const int tx  = tid & 15;
    const int ty  = tid >> 4;
    const int q0  = blockIdx.x * 64;
    const int h   = blockIdx.y;
    const int b   = blockIdx.z;
    const float scale = 0.17677669529663687f;  // 1/sqrt(32)
    const int base = (b * SEQ) * D_MODEL + h * HEAD_DIM;

    // Load Q tile (pre-scaled)
    for (int i = tid; i < 64 * 32; i += 256) {
        int q = i >> 5, d = i & 31;
        Qs[q][d] = Q[base + (q0 + q) * D_MODEL + d] * scale;
    }

    float m[4], l[4], o[4][2];
    #pragma unroll
    for (int i = 0; i < 4; i++) { m[i] = -1e30f; l[i] = 0.f; o[i][0] = 0.f; o[i][1] = 0.f; }

    for (int kt = 0; kt < SEQ; kt += 64) {
        for (int i = tid; i < 64 * 32; i += 256) {
            int k = i >> 5, d = i & 31;
            Ks[k][d] = K[base + (kt + k) * D_MODEL + d];
            Vs[k][d] = V[base + (kt + k) * D_MODEL + d];
        }
        __syncthreads();

        // S = Q K^T (4x4 frag per thread)
        float s[4][4] = {};
        #pragma unroll
        for (int d = 0; d < 32; d++) {
            float a[4], kk[4];
            #pragma unroll
            for (int i = 0; i < 4; i++) a[i]  = Qs[ty * 4 + i][d];
            #pragma unroll
            for (int j = 0; j < 4; j++) kk[j] = Ks[tx * 4 + j][d];
            #pragma unroll
            for (int i = 0; i < 4; i++)
                #pragma unroll
                for (int j = 0; j < 4; j++)
                    s[i][j] += a[i] * kk[j];
        }

        // Online softmax; P staged in smem
        #pragma unroll
        for (int i = 0; i < 4; i++) {
            float mt = fmaxf(fmaxf(s[i][0], s[i][1]), fmaxf(s[i][2], s[i][3]));
            #pragma unroll
            for (int off = 1; off < 16; off <<= 1)
                mt = fmaxf(mt, __shfl_xor_sync(0xffffffffu, mt, off));
            const float mn    = fmaxf(m[i], mt);
            const float alpha = __expf(m[i] - mn);
            m[i] = mn;
            float rs = 0.f;
            #pragma unroll
            for (int j = 0; j < 4; j++) {
                const float p = __expf(s[i][j] - mn);
                Ps[ty * 4 + i][tx * 4 + j] = p;
                rs += p;
            }
            #pragma unroll
            for (int off = 1; off < 16; off <<= 1)
                rs += __shfl_xor_sync(0xffffffffu, rs, off);
            l[i] = l[i] * alpha + rs;
            o[i][0] *= alpha;
            o[i][1] *= alpha;
        }
        __syncthreads();

        // O += P @ V   (thread owns 4 queries x 2 dims: d = tx*2, tx*2+1)
        #pragma unroll 4
        for (int k = 0; k < 64; k++) {
            const float2 v2 = *reinterpret_cast<const float2*>(&Vs[k][tx * 2]);
            #pragma unroll
            for (int i = 0; i < 4; i++) {
                const float p = Ps[ty * 4 + i][k];
                o[i][0] += p * v2.x;
                o[i][1] += p * v2.y;
            }
        }
        __syncthreads();
    }

    #pragma unroll
    for (int i = 0; i < 4; i++) {
        const float inv = 1.0f / l[i];
        const int q = q0 + ty * 4 + i;
        float2 r = make_float2(o[i][0] * inv, o[i][1] * inv);
        *reinterpret_cast<float2*>(&O[base + q * D_MODEL + tx * 2]) = r;
    }
}

// ---------------------------------------------------------------------------
// Launch
// ---------------------------------------------------------------------------
extern "C" void kernel_launch(void* const* d_in, const int* in_sizes, int n_in,
                              void* d_out, int out_size)
{
    const float* x    = (const float*)d_in[0];
    const float* ln1s = (const float*)d_in[1];
    const float* ln1b = (const float*)d_in[2];
    const float* wq   = (const float*)d_in[3];
    const float* bq   = (const float*)d_in[4];
    const float* wk   = (const float*)d_in[5];
    const float* bk   = (const float*)d_in[6];
    const float* wv   = (const float*)d_in[7];
    const float* bv   = (const float*)d_in[8];
    const float* wo   = (const float*)d_in[9];
    const float* bo   = (const float*)d_in[10];
    const float* ln2s = (const float*)d_in[11];
    const float* ln2b = (const float*)d_in[12];
    const float* w1   = (const float*)d_in[13];
    const float* b1   = (const float*)d_in[14];
    const float* w2   = (const float*)d_in[15];
    const float* b2   = (const float*)d_in[16];

    float* X = (float*)d_out;

    float *normed, *q, *k, *v, *attn, *ffh;
    cudaGetSymbolAddress((void**)&normed, g_normed);
    cudaGetSymbolAddress((void**)&q,      g_q);
    cudaGetSymbolAddress((void**)&k,      g_k);
    cudaGetSymbolAddress((void**)&v,      g_v);
    cudaGetSymbolAddress((void**)&attn,   g_attn);
    cudaGetSymbolAddress((void**)&ffh,    g_ffh);

    // x -> output buffer (residual stream lives in d_out)
    cudaMemcpyAsync(X, x, (size_t)NTOK * D_MODEL * sizeof(float),
                    cudaMemcpyDeviceToDevice);

    const dim3 gemm_dd(D_MODEL / 64, NTOK / 64);  // (4, 128)
    const dim3 gemm_df(D_FF / 64,    NTOK / 64);  // (16, 128)
    const dim3 attn_grid(SEQ / 64, N_HEADS, BATCH);

    for (int l = 0; l < N_LAYERS; l++) {
        const int wo_off = l * D_MODEL * D_MODEL;
        ln_kernel<<<NTOK, 256>>>(X, ln1s + l * D_MODEL, ln1b + l * D_MODEL, normed);

        gemm_kernel<false, false><<<gemm_dd, 256>>>(normed, wq + wo_off, bq + l * D_MODEL, q, D_MODEL, D_MODEL);
        gemm_kernel<false, false><<<gemm_dd, 256>>>(normed, wk + wo_off, bk + l * D_MODEL, k, D_MODEL, D_MODEL);
        gemm_kernel<false, false><<<gemm_dd, 256>>>(normed, wv + wo_off, bv + l * D_MODEL, v, D_MODEL, D_MODEL);

        attn_kernel<<<attn_grid, 256>>>(q, k, v, attn);

        gemm_kernel<false, true><<<gemm_dd, 256>>>(attn, wo + wo_off, bo + l * D_MODEL, X, D_MODEL, D_MODEL);

        ln_kernel<<<NTOK, 256>>>(X, ln2s + l * D_MODEL, ln2b + l * D_MODEL, normed);

        gemm_kernel<true, false><<<gemm_df, 256>>>(normed, w1 + l * D_MODEL * D_FF, b1 + l * D_FF, ffh, D_MODEL, D_FF);
        gemm_kernel<false, true><<<gemm_dd, 256>>>(ffh, w2 + l * D_FF * D_MODEL, b2 + l * D_MODEL, X, D_FF, D_MODEL);
    }
}

// round 2
// speedup vs baseline: 2.8026x; 2.8026x over previous
#include <cuda_runtime.h>
#include <math.h>
#include <stdint.h>

#define D_MODEL   256
#define N_LAYERS  6
#define N_HEADS   8
#define D_FF      1024
#define HEAD_DIM  32
#define BATCH     4
#define SEQ       2048
#define NTOK      (BATCH * SEQ)   // 8192

// ---------------------------------------------------------------------------
// Scratch
// ---------------------------------------------------------------------------
__device__ float g_normed[NTOK * D_MODEL];
__device__ float g_q[NTOK * D_MODEL];
__device__ float g_k[NTOK * D_MODEL];
__device__ float g_v[NTOK * D_MODEL];
__device__ float g_attn[NTOK * D_MODEL];
__device__ float g_ffh[NTOK * D_FF];

// ---------------------------------------------------------------------------
// tf32 helpers
// ---------------------------------------------------------------------------
__device__ __forceinline__ uint32_t f2tf32(float x) {
    uint32_t r;
    asm("cvt.rna.tf32.f32 %0, %1;" : "=r"(r) : "f"(x));
    return r;
}

__device__ __forceinline__ void mma_tf32(float* c, const uint32_t* a, const uint32_t* b) {
    asm volatile(
        "mma.sync.aligned.m16n8k8.row.col.f32.tf32.tf32.f32 "
        "{%0,%1,%2,%3},{%4,%5,%6,%7},{%8,%9},{%0,%1,%2,%3};\n"
        : "+f"(c[0]), "+f"(c[1]), "+f"(c[2]), "+f"(c[3])
        : "r"(a[0]), "r"(a[1]), "r"(a[2]), "r"(a[3]),
          "r"(b[0]), "r"(b[1]));
}

// ---------------------------------------------------------------------------
// LayerNorm: one block (256 threads) per row of 256 elements
// ---------------------------------------------------------------------------
__global__ void __launch_bounds__(256) ln_kernel(
    const float* __restrict__ X, const float* __restrict__ S,
    const float* __restrict__ Bb, float* __restrict__ Y)
{
    const int row = blockIdx.x;
    const int tid = threadIdx.x;
    const float v = X[row * D_MODEL + tid];

    __shared__ float red[16];
    float s1 = v, s2 = v * v;
    #pragma unroll
    for (int off = 16; off > 0; off >>= 1) {
        s1 += __shfl_xor_sync(0xffffffffu, s1, off);
        s2 += __shfl_xor_sync(0xffffffffu, s2, off);
    }
    const int w = tid >> 5;
    if ((tid & 31) == 0) { red[w] = s1; red[8 + w] = s2; }
    __syncthreads();
    float sum = 0.f, sq = 0.f;
    #pragma unroll
    for (int i = 0; i < 8; i++) { sum += red[i]; sq += red[8 + i]; }
    const float mu  = sum * (1.0f / D_MODEL);
    const float var = sq * (1.0f / D_MODEL) - mu * mu;
    const float inv = rsqrtf(var + 1e-5f);
    Y[row * D_MODEL + tid] = (v - mu) * inv * S[tid] + Bb[tid];
}

// ---------------------------------------------------------------------------
// tf32 tensor-core GEMM body: C[rows,M] = A[rows,K] @ W[K,M] + bias
// Block tile 128x64, BK=32, 256 threads (8 warps as 4m x 2n, 32x32 per warp).
// ---------------------------------------------------------------------------
template <bool GELU, bool RES>
__device__ __forceinline__ void gemm_body(
    const float* __restrict__ A, const float* __restrict__ W,
    const float* __restrict__ bias, float* __restrict__ C,
    int K, int M)
{
    __shared__ __align__(16) uint32_t As[128 * 36];  // pitch 36 (== 4 mod 32)
    __shared__ __align__(16) uint32_t Ws[32 * 72];   // pitch 72 (== 8 mod 32)

    const int tid  = threadIdx.x;
    const int lane = tid & 31;
    const int wid  = tid >> 5;
    const int warp_m = wid >> 1;          // 0..3
    const int warp_n = wid & 1;           // 0..1
    const int r0   = lane >> 2;           // 0..7
    const int quad = lane & 3;            // 0..3
    const int row0 = blockIdx.y * 128;
    const int col0 = blockIdx.x * 64;

    float acc[2][4][4] = {};

    for (int k0 = 0; k0 < K; k0 += 32) {
        // Load A tile 128x32 (vectorized, cvt to tf32)
        #pragma unroll
        for (int i = 0; i < 4; i++) {
            int e = tid + i * 256;              // 0..1023
            int r = e >> 3, c4 = e & 7;
            float4 v = *reinterpret_cast<const float4*>(&A[(row0 + r) * K + k0 + c4 * 4]);
            uint4 u = make_uint4(f2tf32(v.x), f2tf32(v.y), f2tf32(v.z), f2tf32(v.w));
            *reinterpret_cast<uint4*>(&As[r * 36 + c4 * 4]) = u;
        }
        // Load W tile 32x64
        #pragma unroll
        for (int i = 0; i < 2; i++) {
            int e = tid + i * 256;              // 0..511
            int r = e >> 4, c4 = e & 15;
            float4 v = *reinterpret_cast<const float4*>(&W[(k0 + r) * M + col0 + c4 * 4]);
            uint4 u = make_uint4(f2tf32(v.x), f2tf32(v.y), f2tf32(v.z), f2tf32(v.w));
            *reinterpret_cast<uint4*>(&Ws[r * 72 + c4 * 4]) = u;
        }
        __syncthreads();

        #pragma unroll
        for (int ks = 0; ks < 4; ks++) {
            const int kk = ks * 8;
            uint32_t a[2][4], b[4][2];
            #pragma unroll
            for (int mi = 0; mi < 2; mi++) {
                const int rb = warp_m * 32 + mi * 16 + r0;
                a[mi][0] = As[rb * 36 + kk + quad];
                a[mi][1] = As[(rb + 8) * 36 + kk + quad];
                a[mi][2] = As[rb * 36 + kk + 4 + quad];
                a[mi][3] = As[(rb + 8) * 36 + kk + 4 + quad];
            }
            #pragma unroll
            for (int ni = 0; ni < 4; ni++) {
                const int cb = warp_n * 32 + ni * 8 + r0;
                b[ni][0] = Ws[(kk + quad) * 72 + cb];
                b[ni][1] = Ws[(kk + 4 + quad) * 72 + cb];
            }
            #pragma unroll
            for (int mi = 0; mi < 2; mi++)
                #pragma unroll
                for (int ni = 0; ni < 4; ni++)
                    mma_tf32(acc[mi][ni], a[mi], b[ni]);
        }
        __syncthreads();
    }

    // Epilogue
    #pragma unroll
    for (int mi = 0; mi < 2; mi++) {
        #pragma unroll
        for (int ni = 0; ni < 4; ni++) {
            const int r = row0 + warp_m * 32 + mi * 16 + r0;
            const int c = col0 + warp_n * 32 + ni * 8 + 2 * quad;
            const float bx = bias[c], by = bias[c + 1];
            float v0 = acc[mi][ni][0] + bx;
            float v1 = acc[mi][ni][1] + by;
            float v2 = acc[mi][ni][2] + bx;
            float v3 = acc[mi][ni][3] + by;
            if (GELU) {
                v0 = 0.5f * v0 * (1.0f + erff(v0 * 0.70710678118654752f));
                v1 = 0.5f * v1 * (1.0f + erff(v1 * 0.70710678118654752f));
                v2 = 0.5f * v2 * (1.0f + erff(v2 * 0.70710678118654752f));
                v3 = 0.5f * v3 * (1.0f + erff(v3 * 0.70710678118654752f));
            }
            if (RES) {
                float2 e0 = *reinterpret_cast<const float2*>(&C[r * M + c]);
                float2 e1 = *reinterpret_cast<const float2*>(&C[(r + 8) * M + c]);
                v0 += e0.x; v1 += e0.y; v2 += e1.x; v3 += e1.y;
            }
            *reinterpret_cast<float2*>(&C[r * M + c])       = make_float2(v0, v1);
            *reinterpret_cast<float2*>(&C[(r + 8) * M + c]) = make_float2(v2, v3);
        }
    }
}

template <bool GELU, bool RES>
__global__ void __launch_bounds__(256) gemm_kernel(
    const float* __restrict__ A, const float* __restrict__ W,
    const float* __restrict__ bias, float* __restrict__ C, int K, int M)
{
    gemm_body<GELU, RES>(A, W, bias, C, K, M);
}

// Fused QKV: blockIdx.z selects which projection
__global__ void __launch_bounds__(256) qkv_kernel(
    const float* __restrict__ A,
    const float* __restrict__ wq, const float* __restrict__ wk, const float* __restrict__ wv,
    const float* __restrict__ bq, const float* __restrict__ bk, const float* __restrict__ bv,
    float* __restrict__ q, float* __restrict__ k, float* __restrict__ v)
{
    const float* W; const float* B; float* C;
    if (blockIdx.z == 0)      { W = wq; B = bq; C = q; }
    else if (blockIdx.z == 1) { W = wk; B = bk; C = k; }
    else                      { W = wv; B = bv; C = v; }
    gemm_body<false, false>(A, W, B, C, D_MODEL, D_MODEL);
}

// ---------------------------------------------------------------------------
// Flash attention on HMMA(tf32): block = (b,h,64 queries), 4 warps.
// Each warp: 16 queries x 64 keys (S), then P@V into 16x32.
// ---------------------------------------------------------------------------
__global__ void __launch_bounds__(128) attn_kernel(
    const float* __restrict__ Q, const float* __restrict__ K,
    const float* __restrict__ V, float* __restrict__ O)
{
    __shared__ __align__(16) uint32_t Qs[64 * 36];  // pitch 36 (4 mod 32)
    __shared__ __align__(16) uint32_t Ks[64 * 36];  // pitch 36
    __shared__ __align__(16) uint32_t Vs[64 * 40];  // pitch 40 (8 mod 32)
    __shared__ __align__(16) uint32_t Ps[64 * 68];  // pitch 68 (4 mod 32)

    const int tid  = threadIdx.x;
    const int lane = tid & 31;
    const int w    = tid >> 5;            // warp 0..3
    const int r0   = lane >> 2;           // 0..7
    const int quad = lane & 3;            // 0..3
    const int q0   = blockIdx.x * 64;
    const int h    = blockIdx.y;
    const int b    = blockIdx.z;
    const float scale = 0.17677669529663687f;  // 1/sqrt(32)
    const int base = (b * SEQ) * D_MODEL + h * HEAD_DIM;

    // Load Q tile (pre-scaled, tf32)
    #pragma unroll
    for (int i = 0; i < 4; i++) {
        int e = tid + i * 128;            // 0..511 float4 chunks
        int r = e >> 3, c4 = e & 7;
        float4 v = *reinterpret_cast<const float4*>(&Q[base + (q0 + r) * D_MODEL + c4 * 4]);
        uint4 u = make_uint4(f2tf32(v.x * scale), f2tf32(v.y * scale),
                             f2tf32(v.z * scale), f2tf32(v.w * scale));
        *reinterpret_cast<uint4*>(&Qs[r * 36 + c4 * 4]) = u;
    }

    float m0 = -1e30f, m1 = -1e30f, l0 = 0.f, l1 = 0.f;
    float o[4][4] = {};
    const int rb = w * 16 + r0;           // this thread's query row pair base

    for (int kt = 0; kt < SEQ; kt += 64) {
        __syncthreads();   // previous PV done reading Vs (also covers Q-load on iter 0)
        #pragma unroll
        for (int i = 0; i < 4; i++) {
            int e = tid + i * 128;
            int r = e >> 3, c4 = e & 7;
            const int g = base + (kt + r) * D_MODEL + c4 * 4;
            float4 kv = *reinterpret_cast<const float4*>(&K[g]);
            float4 vv = *reinterpret_cast<const float4*>(&V[g]);
            *reinterpret_cast<uint4*>(&Ks[r * 36 + c4 * 4]) =
                make_uint4(f2tf32(kv.x), f2tf32(kv.y), f2tf32(kv.z), f2tf32(kv.w));
            *reinterpret_cast<uint4*>(&Vs[r * 40 + c4 * 4]) =
                make_uint4(f2tf32(vv.x), f2tf32(vv.y), f2tf32(vv.z), f2tf32(vv.w));
        }
        __syncthreads();

        // S = Q K^T : per warp 16x64 in 8 n-tiles
        float s[8][4] = {};
        #pragma unroll
        for (int ks = 0; ks < 4; ks++) {
            const int kk = ks * 8;
            uint32_t a[4];
            a[0] = Qs[rb * 36 + kk + quad];
            a[1] = Qs[(rb + 8) * 36 + kk + quad];
            a[2] = Qs[rb * 36 + kk + 4 + quad];
            a[3] = Qs[(rb + 8) * 36 + kk + 4 + quad];
            #pragma unroll
            for (int ni = 0; ni < 8; ni++) {
                uint32_t bb[2];
                const int nb = ni * 8 + r0;
                bb[0] = Ks[nb * 36 + kk + quad];
                bb[1] = Ks[nb * 36 + kk + 4 + quad];
                mma_tf32(s[ni], a, bb);
            }
        }

        // Online softmax over this thread's two rows (rb, rb+8)
        float mt0 = -1e30f, mt1 = -1e30f;
        #pragma unroll
        for (int ni = 0; ni < 8; ni++) {
            mt0 = fmaxf(mt0, fmaxf(s[ni][0], s[ni][1]));
            mt1 = fmaxf(mt1, fmaxf(s[ni][2], s[ni][3]));
        }
        #pragma unroll
        for (int off = 1; off < 4; off <<= 1) {
            mt0 = fmaxf(mt0, __shfl_xor_sync(0xffffffffu, mt0, off));
            mt1 = fmaxf(mt1, __shfl_xor_sync(0xffffffffu, mt1, off));
        }
        const float mn0 = fmaxf(m0, mt0);
        const float mn1 = fmaxf(m1, mt1);
        const float alpha0 = __expf(m0 - mn0);
        const float alpha1 = __expf(m1 - mn1);
        m0 = mn0; m1 = mn1;

        float rs0 = 0.f, rs1 = 0.f;
        #pragma unroll
        for (int ni = 0; ni < 8; ni++) {
            const float p00 = __expf(s[ni][0] - mn0);
            const float p01 = __expf(s[ni][1] - mn0);
            const float p10 = __expf(s[ni][2] - mn1);
            const float p11 = __expf(s[ni][3] - mn1);
            rs0 += p00 + p01;
            rs1 += p10 + p11;
            const int col = ni * 8 + 2 * quad;
            Ps[rb * 68 + col]           = f2tf32(p00);
            Ps[rb * 68 + col + 1]       = f2tf32(p01);
            Ps[(rb + 8) * 68 + col]     = f2tf32(p10);
            Ps[(rb + 8) * 68 + col + 1] = f2tf32(p11);
        }
        #pragma unroll
        for (int off = 1; off < 4; off <<= 1) {
            rs0 += __shfl_xor_sync(0xffffffffu, rs0, off);
            rs1 += __shfl_xor_sync(0xffffffffu, rs1, off);
        }
        l0 = l0 * alpha0 + rs0;
        l1 = l1 * alpha1 + rs1;
        #pragma unroll
        for (int ni = 0; ni < 4; ni++) {
            o[ni][0] *= alpha0; o[ni][1] *= alpha0;
            o[ni][2] *= alpha1; o[ni][3] *= alpha1;
        }
        __syncwarp();   // Ps rows are warp-private; just order write->read

        // O += P @ V : 8 k-steps over keys, 4 n-tiles over 32 dims
        #pragma unroll
        for (int ks = 0; ks < 8; ks++) {
            const int kk = ks * 8;
            uint32_t a[4];
            a[0] = Ps[rb * 68 + kk + quad];
            a[1] = Ps[(rb + 8) * 68 + kk + quad];
            a[2] = Ps[rb * 68 + kk + 4 + quad];
            a[3] = Ps[(rb + 8) * 68 + kk + 4 + quad];
            #pragma unroll
            for (int ni = 0; ni < 4; ni++) {
                uint32_t bb[2];
                const int nb = ni * 8 + r0;
                bb[0] = Vs[(kk + quad) * 40 + nb];
                bb[1] = Vs[(kk + 4 + quad) * 40 + nb];
                mma_tf32(o[ni], a, bb);
            }
        }
    }

    const float inv0 = 1.0f / l0;
    const float inv1 = 1.0f / l1;
    #pragma unroll
    for (int ni = 0; ni < 4; ni++) {
        const int q = q0 + rb;
        const int d = ni * 8 + 2 * quad;
        *reinterpret_cast<float2*>(&O[base + q * D_MODEL + d]) =
            make_float2(o[ni][0] * inv0, o[ni][1] * inv0);
        *reinterpret_cast<float2*>(&O[base + (q + 8) * D_MODEL + d]) =
            make_float2(o[ni][2] * inv1, o[ni][3] * inv1);
    }
}

// ---------------------------------------------------------------------------
// Launch
// ---------------------------------------------------------------------------
extern "C" void kernel_launch(void* const* d_in, const int* in_sizes, int n_in,
                              void* d_out, int out_size)
{
    const float* x    = (const float*)d_in[0];
    const float* ln1s = (const float*)d_in[1];
    const float* ln1b = (const float*)d_in[2];
    const float* wq   = (const float*)d_in[3];
    const float* bq   = (const float*)d_in[4];
    const float* wk   = (const float*)d_in[5];
    const float* bk   = (const float*)d_in[6];
    const float* wv   = (const float*)d_in[7];
    const float* bv   = (const float*)d_in[8];
    const float* wo   = (const float*)d_in[9];
    const float* bo   = (const float*)d_in[10];
    const float* ln2s = (const float*)d_in[11];
    const float* ln2b = (const float*)d_in[12];
    const float* w1   = (const float*)d_in[13];
    const float* b1   = (const float*)d_in[14];
    const float* w2   = (const float*)d_in[15];
    const float* b2   = (const float*)d_in[16];

    float* X = (float*)d_out;

    float *normed, *q, *k, *v, *attn, *ffh;
    cudaGetSymbolAddress((void**)&normed, g_normed);
    cudaGetSymbolAddress((void**)&q,      g_q);
    cudaGetSymbolAddress((void**)&k,      g_k);
    cudaGetSymbolAddress((void**)&v,      g_v);
    cudaGetSymbolAddress((void**)&attn,   g_attn);
    cudaGetSymbolAddress((void**)&ffh,    g_ffh);

    cudaMemcpyAsync(X, x, (size_t)NTOK * D_MODEL * sizeof(float),
                    cudaMemcpyDeviceToDevice);

    const dim3 gemm_dd(D_MODEL / 64, NTOK / 128);     // (4, 64)
    const dim3 gemm_df(D_FF / 64,    NTOK / 128);     // (16, 64)
    const dim3 qkv_grid(D_MODEL / 64, NTOK / 128, 3); // (4, 64, 3)
    const dim3 attn_grid(SEQ / 64, N_HEADS, BATCH);

    for (int l = 0; l < N_LAYERS; l++) {
        const int wdd = l * D_MODEL * D_MODEL;
        ln_kernel<<<NTOK, 256>>>(X, ln1s + l * D_MODEL, ln1b + l * D_MODEL, normed);

        qkv_kernel<<<qkv_grid, 256>>>(normed,
                                      wq + wdd, wk + wdd, wv + wdd,
                                      bq + l * D_MODEL, bk + l * D_MODEL, bv + l * D_MODEL,
                                      q, k, v);

        attn_kernel<<<attn_grid, 128>>>(q, k, v, attn);

        gemm_kernel<false, true><<<gemm_dd, 256>>>(attn, wo + wdd, bo + l * D_MODEL, X, D_MODEL, D_MODEL);

        ln_kernel<<<NTOK, 256>>>(X, ln2s + l * D_MODEL, ln2b + l * D_MODEL, normed);

        gemm_kernel<true, false><<<gemm_df, 256>>>(normed, w1 + l * D_MODEL * D_FF, b1 + l * D_FF, ffh, D_MODEL, D_FF);
        gemm_kernel<false, true><<<gemm_dd, 256>>>(ffh, w2 + l * D_FF * D_MODEL, b2 + l * D_MODEL, X, D_FF, D_MODEL);
    }
}

// round 3
// speedup vs baseline: 3.0538x; 1.0896x over previous
#include <cuda_runtime.h>
#include <math.h>
#include <stdint.h>

#define D_MODEL   256
#define N_LAYERS  6
#define N_HEADS   8
#define D_FF      1024
#define HEAD_DIM  32
#define BATCH     4
#define SEQ       2048
#define NTOK      (BATCH * SEQ)   // 8192

// ---------------------------------------------------------------------------
// Scratch
// ---------------------------------------------------------------------------
__device__ float g_normed[NTOK * D_MODEL];
__device__ float g_q[NTOK * D_MODEL];
__device__ float g_k[NTOK * D_MODEL];
__device__ float g_v[NTOK * D_MODEL];
__device__ float g_attn[NTOK * D_MODEL];
__device__ float g_ffh[NTOK * D_FF];

// ---------------------------------------------------------------------------
// Helpers
// ---------------------------------------------------------------------------
__device__ __forceinline__ uint32_t smem_u32(const void* p) {
    return (uint32_t)__cvta_generic_to_shared(p);
}
#define CPA16(dst_u32, src_ptr) \
    asm volatile("cp.async.cg.shared.global [%0], [%1], 16;\n" :: "r"(dst_u32), "l"(src_ptr))
#define CPA_COMMIT() asm volatile("cp.async.commit_group;\n" ::)
#define CPA_WAIT1()  asm volatile("cp.async.wait_group 1;\n" ::)
#define CPA_WAIT0()  asm volatile("cp.async.wait_group 0;\n" ::)

// HMMA m16n8k8 tf32 (raw fp32 bits: HW truncates mantissa -> acceptable error)
__device__ __forceinline__ void mma_tf32(float* c, const uint32_t* a, const uint32_t* b) {
    asm volatile(
        "mma.sync.aligned.m16n8k8.row.col.f32.tf32.tf32.f32 "
        "{%0,%1,%2,%3},{%4,%5,%6,%7},{%8,%9},{%0,%1,%2,%3};\n"
        : "+f"(c[0]), "+f"(c[1]), "+f"(c[2]), "+f"(c[3])
        : "r"(a[0]), "r"(a[1]), "r"(a[2]), "r"(a[3]),
          "r"(b[0]), "r"(b[1]));
}

// ---------------------------------------------------------------------------
// LayerNorm: one block (256 threads) per row of 256 elements
// ---------------------------------------------------------------------------
__global__ void __launch_bounds__(256) ln_kernel(
    const float* __restrict__ X, const float* __restrict__ S,
    const float* __restrict__ Bb, float* __restrict__ Y)
{
    const int row = blockIdx.x;
    const int tid = threadIdx.x;
    const float v = X[row * D_MODEL + tid];

    __shared__ float red[16];
    float s1 = v, s2 = v * v;
    #pragma unroll
    for (int off = 16; off > 0; off >>= 1) {
        s1 += __shfl_xor_sync(0xffffffffu, s1, off);
        s2 += __shfl_xor_sync(0xffffffffu, s2, off);
    }
    const int w = tid >> 5;
    if ((tid & 31) == 0) { red[w] = s1; red[8 + w] = s2; }
    __syncthreads();
    float sum = 0.f, sq = 0.f;
    #pragma unroll
    for (int i = 0; i < 8; i++) { sum += red[i]; sq += red[8 + i]; }
    const float mu  = sum * (1.0f / D_MODEL);
    const float var = sq * (1.0f / D_MODEL) - mu * mu;
    const float inv = rsqrtf(var + 1e-5f);
    Y[row * D_MODEL + tid] = (v - mu) * inv * S[tid] + Bb[tid];
}

// ---------------------------------------------------------------------------
// tf32 GEMM, cp.async double-buffered: C[rows,M] = A @ W + bias
// Block 128x64, BK=32, 256 threads (8 warps 4m x 2n, 32x32 per warp).
// Dynamic smem: As[2][128*36], Ws[2][32*72]  (55296 B)
// ---------------------------------------------------------------------------
#define GEMM_SMEM_BYTES ((2 * 128 * 36 + 2 * 32 * 72) * 4)

template <bool GELU, bool RES>
__device__ __forceinline__ void gemm_body(
    const float* __restrict__ A, const float* __restrict__ W,
    const float* __restrict__ bias, float* __restrict__ C,
    int K, int M)
{
    extern __shared__ __align__(16) uint32_t dynsmem[];
    uint32_t* As = dynsmem;                 // [2][128*36]
    uint32_t* Ws = dynsmem + 2 * 128 * 36;  // [2][32*72]

    const int tid  = threadIdx.x;
    const int lane = tid & 31;
    const int wid  = tid >> 5;
    const int warp_m = wid >> 1;
    const int warp_n = wid & 1;
    const int r0   = lane >> 2;
    const int quad = lane & 3;
    const int row0 = blockIdx.y * 128;
    const int col0 = blockIdx.x * 64;

    const int a_r = tid >> 3, a_c4 = tid & 7;   // A: rows a_r + 32i, 16B col a_c4
    const int w_r = tid >> 4, w_c4 = tid & 15;  // W: rows w_r + 16i

    float acc[2][4][4] = {};

    // stage loader
    auto load_stage = [&](int k0, int s) {
        const float* Ab = A + (size_t)row0 * K + k0;
        uint32_t* Asb = As + s * (128 * 36);
        #pragma unroll
        for (int i = 0; i < 4; i++) {
            int r = a_r + i * 32;
            CPA16(smem_u32(&Asb[r * 36 + a_c4 * 4]), Ab + (size_t)r * K + a_c4 * 4);
        }
        const float* Wb = W + (size_t)k0 * M + col0;
        uint32_t* Wsb = Ws + s * (32 * 72);
        #pragma unroll
        for (int i = 0; i < 2; i++) {
            int r = w_r + i * 16;
            CPA16(smem_u32(&Wsb[r * 72 + w_c4 * 4]), Wb + (size_t)r * M + w_c4 * 4);
        }
        CPA_COMMIT();
    };

    load_stage(0, 0);
    const int nk = K >> 5;

    for (int it = 0; it < nk; ++it) {
        const int s = it & 1;
        if (it + 1 < nk) { load_stage((it + 1) * 32, s ^ 1); CPA_WAIT1(); }
        else             { CPA_WAIT0(); }
        __syncthreads();

        const uint32_t* Asb = As + s * (128 * 36);
        const uint32_t* Wsb = Ws + s * (32 * 72);
        #pragma unroll
        for (int ks = 0; ks < 4; ks++) {
            const int kk = ks * 8;
            uint32_t a[2][4], b[4][2];
            #pragma unroll
            for (int mi = 0; mi < 2; mi++) {
                const int rb = warp_m * 32 + mi * 16 + r0;
                a[mi][0] = Asb[rb * 36 + kk + quad];
                a[mi][1] = Asb[(rb + 8) * 36 + kk + quad];
                a[mi][2] = Asb[rb * 36 + kk + 4 + quad];
                a[mi][3] = Asb[(rb + 8) * 36 + kk + 4 + quad];
            }
            #pragma unroll
            for (int ni = 0; ni < 4; ni++) {
                const int cb = warp_n * 32 + ni * 8 + r0;
                b[ni][0] = Wsb[(kk + quad) * 72 + cb];
                b[ni][1] = Wsb[(kk + 4 + quad) * 72 + cb];
            }
            #pragma unroll
            for (int mi = 0; mi < 2; mi++)
                #pragma unroll
                for (int ni = 0; ni < 4; ni++)
                    mma_tf32(acc[mi][ni], a[mi], b[ni]);
        }
        __syncthreads();
    }

    #pragma unroll
    for (int mi = 0; mi < 2; mi++) {
        #pragma unroll
        for (int ni = 0; ni < 4; ni++) {
            const int r = row0 + warp_m * 32 + mi * 16 + r0;
            const int c = col0 + warp_n * 32 + ni * 8 + 2 * quad;
            const float bx = bias[c], by = bias[c + 1];
            float v0 = acc[mi][ni][0] + bx;
            float v1 = acc[mi][ni][1] + by;
            float v2 = acc[mi][ni][2] + bx;
            float v3 = acc[mi][ni][3] + by;
            if (GELU) {
                v0 = 0.5f * v0 * (1.0f + erff(v0 * 0.70710678118654752f));
                v1 = 0.5f * v1 * (1.0f + erff(v1 * 0.70710678118654752f));
                v2 = 0.5f * v2 * (1.0f + erff(v2 * 0.70710678118654752f));
                v3 = 0.5f * v3 * (1.0f + erff(v3 * 0.70710678118654752f));
            }
            if (RES) {
                float2 e0 = *reinterpret_cast<const float2*>(&C[(size_t)r * M + c]);
                float2 e1 = *reinterpret_cast<const float2*>(&C[(size_t)(r + 8) * M + c]);
                v0 += e0.x; v1 += e0.y; v2 += e1.x; v3 += e1.y;
            }
            *reinterpret_cast<float2*>(&C[(size_t)r * M + c])       = make_float2(v0, v1);
            *reinterpret_cast<float2*>(&C[(size_t)(r + 8) * M + c]) = make_float2(v2, v3);
        }
    }
}

template <bool GELU, bool RES>
__global__ void __launch_bounds__(256) gemm_kernel(
    const float* __restrict__ A, const float* __restrict__ W,
    const float* __restrict__ bias, float* __restrict__ C, int K, int M)
{
    gemm_body<GELU, RES>(A, W, bias, C, K, M);
}

__global__ void __launch_bounds__(256) qkv_kernel(
    const float* __restrict__ A,
    const float* __restrict__ wq, const float* __restrict__ wk, const float* __restrict__ wv,
    const float* __restrict__ bq, const float* __restrict__ bk, const float* __restrict__ bv,
    float* __restrict__ q, float* __restrict__ k, float* __restrict__ v)
{
    const float* W; const float* B; float* C;
    if (blockIdx.z == 0)      { W = wq; B = bq; C = q; }
    else if (blockIdx.z == 1) { W = wk; B = bk; C = k; }
    else                      { W = wv; B = bv; C = v; }
    gemm_body<false, false>(A, W, B, C, D_MODEL, D_MODEL);
}

// ---------------------------------------------------------------------------
// Flash attention (HMMA tf32) with cp.async double-buffered K/V tiles.
// Block = (b, h, 64 queries), 4 warps; warp owns 16 query rows.
// Dynamic smem: Qs[64*36] Ks[2][64*36] Vs[2][64*40] Ps[64*68] = 65536 B
// ---------------------------------------------------------------------------
#define ATTN_SMEM_BYTES ((64 * 36 + 2 * 64 * 36 + 2 * 64 * 40 + 64 * 68) * 4)

__global__ void __launch_bounds__(128) attn_kernel(
    const float* __restrict__ Q, const float* __restrict__ K,
    const float* __restrict__ V, float* __restrict__ O)
{
    extern __shared__ __align__(16) uint32_t dyn[];
    uint32_t* Qs = dyn;                      // 64*36
    uint32_t* Ks = Qs + 64 * 36;             // [2][64*36]
    uint32_t* Vs = Ks + 2 * 64 * 36;         // [2][64*40]
    uint32_t* Ps = Vs + 2 * 64 * 40;         // 64*68

    const int tid  = threadIdx.x;
    const int lane = tid & 31;
    const int w    = tid >> 5;
    const int r0   = lane >> 2;
    const int quad = lane & 3;
    const int q0   = blockIdx.x * 64;
    const int h    = blockIdx.y;
    const int b    = blockIdx.z;
    const float scale = 0.17677669529663687f;  // 1/sqrt(32)
    const int base = (b * SEQ) * D_MODEL + h * HEAD_DIM;

    const int kv_r = tid >> 3, kv_c4 = tid & 7;  // rows kv_r + 16i

    auto load_kv = [&](int kt, int s) {
        uint32_t* Ksb = Ks + s * (64 * 36);
        uint32_t* Vsb = Vs + s * (64 * 40);
        #pragma unroll
        for (int i = 0; i < 4; i++) {
            const int r = kv_r + i * 16;
            const float* g = &K[base + (kt + r) * D_MODEL + kv_c4 * 4];
            const float* g2 = &V[base + (kt + r) * D_MODEL + kv_c4 * 4];
            CPA16(smem_u32(&Ksb[r * 36 + kv_c4 * 4]), g);
            CPA16(smem_u32(&Vsb[r * 40 + kv_c4 * 4]), g2);
        }
        CPA_COMMIT();
    };

    load_kv(0, 0);

    // Load Q tile (pre-scaled, raw fp32 bits)
    #pragma unroll
    for (int i = 0; i < 4; i++) {
        int e = tid + i * 128;
        int r = e >> 3, c4 = e & 7;
        float4 v = *reinterpret_cast<const float4*>(&Q[base + (q0 + r) * D_MODEL + c4 * 4]);
        uint4 u = make_uint4(__float_as_uint(v.x * scale), __float_as_uint(v.y * scale),
                             __float_as_uint(v.z * scale), __float_as_uint(v.w * scale));
        *reinterpret_cast<uint4*>(&Qs[r * 36 + c4 * 4]) = u;
    }

    float m0 = -1e30f, m1 = -1e30f, l0 = 0.f, l1 = 0.f;
    float o[4][4] = {};
    const int rb = w * 16 + r0;
    const int NIT = SEQ / 64;

    for (int it = 0; it < NIT; ++it) {
        const int s = it & 1;
        __syncthreads();   // prior PV done reading Vs[s^1] before overwrite
        if (it + 1 < NIT) { load_kv((it + 1) * 64, s ^ 1); CPA_WAIT1(); }
        else              { CPA_WAIT0(); }
        __syncthreads();   // stage s visible to all warps

        const uint32_t* Ksb = Ks + s * (64 * 36);
        const uint32_t* Vsb = Vs + s * (64 * 40);

        // S = Q K^T : per warp 16x64
        float sc[8][4] = {};
        #pragma unroll
        for (int ks = 0; ks < 4; ks++) {
            const int kk = ks * 8;
            uint32_t a[4];
            a[0] = Qs[rb * 36 + kk + quad];
            a[1] = Qs[(rb + 8) * 36 + kk + quad];
            a[2] = Qs[rb * 36 + kk + 4 + quad];
            a[3] = Qs[(rb + 8) * 36 + kk + 4 + quad];
            #pragma unroll
            for (int ni = 0; ni < 8; ni++) {
                uint32_t bb[2];
                const int nb = ni * 8 + r0;
                bb[0] = Ksb[nb * 36 + kk + quad];
                bb[1] = Ksb[nb * 36 + kk + 4 + quad];
                mma_tf32(sc[ni], a, bb);
            }
        }

        // Online softmax (two rows: rb, rb+8)
        float mt0 = -1e30f, mt1 = -1e30f;
        #pragma unroll
        for (int ni = 0; ni < 8; ni++) {
            mt0 = fmaxf(mt0, fmaxf(sc[ni][0], sc[ni][1]));
            mt1 = fmaxf(mt1, fmaxf(sc[ni][2], sc[ni][3]));
        }
        #pragma unroll
        for (int off = 1; off < 4; off <<= 1) {
            mt0 = fmaxf(mt0, __shfl_xor_sync(0xffffffffu, mt0, off));
            mt1 = fmaxf(mt1, __shfl_xor_sync(0xffffffffu, mt1, off));
        }
        const float mn0 = fmaxf(m0, mt0);
        const float mn1 = fmaxf(m1, mt1);
        const float alpha0 = __expf(m0 - mn0);
        const float alpha1 = __expf(m1 - mn1);
        m0 = mn0; m1 = mn1;

        float rs0 = 0.f, rs1 = 0.f;
        #pragma unroll
        for (int ni = 0; ni < 8; ni++) {
            const float p00 = __expf(sc[ni][0] - mn0);
            const float p01 = __expf(sc[ni][1] - mn0);
            const float p10 = __expf(sc[ni][2] - mn1);
            const float p11 = __expf(sc[ni][3] - mn1);
            rs0 += p00 + p01;
            rs1 += p10 + p11;
            const int col = ni * 8 + 2 * quad;
            Ps[rb * 68 + col]           = __float_as_uint(p00);
            Ps[rb * 68 + col + 1]       = __float_as_uint(p01);
            Ps[(rb + 8) * 68 + col]     = __float_as_uint(p10);
            Ps[(rb + 8) * 68 + col + 1] = __float_as_uint(p11);
        }
        #pragma unroll
        for (int off = 1; off < 4; off <<= 1) {
            rs0 += __shfl_xor_sync(0xffffffffu, rs0, off);
            rs1 += __shfl_xor_sync(0xffffffffu, rs1, off);
        }
        l0 = l0 * alpha0 + rs0;
        l1 = l1 * alpha1 + rs1;
        #pragma unroll
        for (int ni = 0; ni < 4; ni++) {
            o[ni][0] *= alpha0; o[ni][1] *= alpha0;
            o[ni][2] *= alpha1; o[ni][3] *= alpha1;
        }
        __syncwarp();   // Ps rows are warp-private

        // O += P @ V
        #pragma unroll
        for (int ks = 0; ks < 8; ks++) {
            const int kk = ks * 8;
            uint32_t a[4];
            a[0] = Ps[rb * 68 + kk + quad];
            a[1] = Ps[(rb + 8) * 68 + kk + quad];
            a[2] = Ps[rb * 68 + kk + 4 + quad];
            a[3] = Ps[(rb + 8) * 68 + kk + 4 + quad];
            #pragma unroll
            for (int ni = 0; ni < 4; ni++) {
                uint32_t bb[2];
                const int nb = ni * 8 + r0;
                bb[0] = Vsb[(kk + quad) * 40 + nb];
                bb[1] = Vsb[(kk + 4 + quad) * 40 + nb];
                mma_tf32(o[ni], a, bb);
            }
        }
    }

    const float inv0 = 1.0f / l0;
    const float inv1 = 1.0f / l1;
    #pragma unroll
    for (int ni = 0; ni < 4; ni++) {
        const int q = q0 + rb;
        const int d = ni * 8 + 2 * quad;
        *reinterpret_cast<float2*>(&O[base + q * D_MODEL + d]) =
            make_float2(o[ni][0] * inv0, o[ni][1] * inv0);
        *reinterpret_cast<float2*>(&O[base + (q + 8) * D_MODEL + d]) =
            make_float2(o[ni][2] * inv1, o[ni][3] * inv1);
    }
}

// ---------------------------------------------------------------------------
// Launch
// ---------------------------------------------------------------------------
extern "C" void kernel_launch(void* const* d_in, const int* in_sizes, int n_in,
                              void* d_out, int out_size)
{
    const float* x    = (const float*)d_in[0];
    const float* ln1s = (const float*)d_in[1];
    const float* ln1b = (const float*)d_in[2];
    const float* wq   = (const float*)d_in[3];
    const float* bq   = (const float*)d_in[4];
    const float* wk   = (const float*)d_in[5];
    const float* bk   = (const float*)d_in[6];
    const float* wv   = (const float*)d_in[7];
    const float* bv   = (const float*)d_in[8];
    const float* wo   = (const float*)d_in[9];
    const float* bo   = (const float*)d_in[10];
    const float* ln2s = (const float*)d_in[11];
    const float* ln2b = (const float*)d_in[12];
    const float* w1   = (const float*)d_in[13];
    const float* b1   = (const float*)d_in[14];
    const float* w2   = (const float*)d_in[15];
    const float* b2   = (const float*)d_in[16];

    float* X = (float*)d_out;

    float *normed, *q, *k, *v, *attn, *ffh;
    cudaGetSymbolAddress((void**)&normed, g_normed);
    cudaGetSymbolAddress((void**)&q,      g_q);
    cudaGetSymbolAddress((void**)&k,      g_k);
    cudaGetSymbolAddress((void**)&v,      g_v);
    cudaGetSymbolAddress((void**)&attn,   g_attn);
    cudaGetSymbolAddress((void**)&ffh,    g_ffh);

    // Allow >48KB dynamic smem (host-side attribute set; not a stream op)
    cudaFuncSetAttribute(gemm_kernel<false, true>,
                         cudaFuncAttributeMaxDynamicSharedMemorySize, GEMM_SMEM_BYTES);
    cudaFuncSetAttribute(gemm_kernel<true, false>,
                         cudaFuncAttributeMaxDynamicSharedMemorySize, GEMM_SMEM_BYTES);
    cudaFuncSetAttribute(qkv_kernel,
                         cudaFuncAttributeMaxDynamicSharedMemorySize, GEMM_SMEM_BYTES);
    cudaFuncSetAttribute(attn_kernel,
                         cudaFuncAttributeMaxDynamicSharedMemorySize, ATTN_SMEM_BYTES);

    cudaMemcpyAsync(X, x, (size_t)NTOK * D_MODEL * sizeof(float),
                    cudaMemcpyDeviceToDevice);

    const dim3 gemm_dd(D_MODEL / 64, NTOK / 128);     // (4, 64)
    const dim3 gemm_df(D_FF / 64,    NTOK / 128);     // (16, 64)
    const dim3 qkv_grid(D_MODEL / 64, NTOK / 128, 3); // (4, 64, 3)
    const dim3 attn_grid(SEQ / 64, N_HEADS, BATCH);

    for (int l = 0; l < N_LAYERS; l++) {
        const int wdd = l * D_MODEL * D_MODEL;
        ln_kernel<<<NTOK, 256>>>(X, ln1s + l * D_MODEL, ln1b + l * D_MODEL, normed);

        qkv_kernel<<<qkv_grid, 256, GEMM_SMEM_BYTES>>>(normed,
                                      wq + wdd, wk + wdd, wv + wdd,
                                      bq + l * D_MODEL, bk + l * D_MODEL, bv + l * D_MODEL,
                                      q, k, v);

        attn_kernel<<<attn_grid, 128, ATTN_SMEM_BYTES>>>(q, k, v, attn);

        gemm_kernel<false, true><<<gemm_dd, 256, GEMM_SMEM_BYTES>>>(
            attn, wo + wdd, bo + l * D_MODEL, X, D_MODEL, D_MODEL);

        ln_kernel<<<NTOK, 256>>>(X, ln2s + l * D_MODEL, ln2b + l * D_MODEL, normed);

        gemm_kernel<true, false><<<gemm_df, 256, GEMM_SMEM_BYTES>>>(
            normed, w1 + l * D_MODEL * D_FF, b1 + l * D_FF, ffh, D_MODEL, D_FF);
        gemm_kernel<false, true><<<gemm_dd, 256, GEMM_SMEM_BYTES>>>(
            ffh, w2 + l * D_FF * D_MODEL, b2 + l * D_MODEL, X, D_FF, D_MODEL);
    }
}

// round 4
// speedup vs baseline: 3.4458x; 1.1284x over previous
#include <cuda_runtime.h>
#include <math.h>
#include <stdint.h>

#define D_MODEL   256
#define N_LAYERS  6
#define N_HEADS   8
#define D_FF      1024
#define HEAD_DIM  32
#define BATCH     4
#define SEQ       2048
#define NTOK      (BATCH * SEQ)   // 8192

// ---------------------------------------------------------------------------
// Scratch
// ---------------------------------------------------------------------------
__device__ float g_normed[NTOK * D_MODEL];
__device__ float g_q[NTOK * D_MODEL];
__device__ float g_k[NTOK * D_MODEL];
__device__ float g_v[NTOK * D_MODEL];
__device__ float g_attn[NTOK * D_MODEL];
__device__ float g_ffh[NTOK * D_FF];

// ---------------------------------------------------------------------------
// Helpers
// ---------------------------------------------------------------------------
__device__ __forceinline__ uint32_t smem_u32(const void* p) {
    return (uint32_t)__cvta_generic_to_shared(p);
}
#define CPA16(dst_u32, src_ptr) \
    asm volatile("cp.async.cg.shared.global [%0], [%1], 16;\n" :: "r"(dst_u32), "l"(src_ptr))
#define CPA_COMMIT() asm volatile("cp.async.commit_group;\n" ::)
#define CPA_WAIT1()  asm volatile("cp.async.wait_group 1;\n" ::)
#define CPA_WAIT0()  asm volatile("cp.async.wait_group 0;\n" ::)

// HMMA m16n8k8 tf32 (raw fp32 bits: HW truncates mantissa)
__device__ __forceinline__ void mma_tf32(float* c, const uint32_t* a, const uint32_t* b) {
    asm volatile(
        "mma.sync.aligned.m16n8k8.row.col.f32.tf32.tf32.f32 "
        "{%0,%1,%2,%3},{%4,%5,%6,%7},{%8,%9},{%0,%1,%2,%3};\n"
        : "+f"(c[0]), "+f"(c[1]), "+f"(c[2]), "+f"(c[3])
        : "r"(a[0]), "r"(a[1]), "r"(a[2]), "r"(a[3]),
          "r"(b[0]), "r"(b[1]));
}

// ldmatrix x4 (b16 path works for tf32: each 8x8 b16 matrix == 8 rows x 4 tf32)
__device__ __forceinline__ void ldsm4(uint32_t* r, uint32_t byte_addr) {
    asm volatile("ldmatrix.sync.aligned.m8n8.x4.shared.b16 {%0,%1,%2,%3}, [%4];\n"
        : "=r"(r[0]), "=r"(r[1]), "=r"(r[2]), "=r"(r[3]) : "r"(byte_addr));
}

// ---------------------------------------------------------------------------
// LayerNorm
// ---------------------------------------------------------------------------
__global__ void __launch_bounds__(256) ln_kernel(
    const float* __restrict__ X, const float* __restrict__ S,
    const float* __restrict__ Bb, float* __restrict__ Y)
{
    const int row = blockIdx.x;
    const int tid = threadIdx.x;
    const float v = X[row * D_MODEL + tid];

    __shared__ float red[16];
    float s1 = v, s2 = v * v;
    #pragma unroll
    for (int off = 16; off > 0; off >>= 1) {
        s1 += __shfl_xor_sync(0xffffffffu, s1, off);
        s2 += __shfl_xor_sync(0xffffffffu, s2, off);
    }
    const int w = tid >> 5;
    if ((tid & 31) == 0) { red[w] = s1; red[8 + w] = s2; }
    __syncthreads();
    float sum = 0.f, sq = 0.f;
    #pragma unroll
    for (int i = 0; i < 8; i++) { sum += red[i]; sq += red[8 + i]; }
    const float mu  = sum * (1.0f / D_MODEL);
    const float var = sq * (1.0f / D_MODEL) - mu * mu;
    const float inv = rsqrtf(var + 1e-5f);
    Y[row * D_MODEL + tid] = (v - mu) * inv * S[tid] + Bb[tid];
}

// ---------------------------------------------------------------------------
// tf32 GEMM: block 128x64, BK=32, 128 threads (4 warps as 2m x 2n, 64x32/warp)
// A-frags via ldmatrix.x4; W-frags scalar LDS. 2-stage cp.async pipeline.
// ---------------------------------------------------------------------------
#define GEMM_SMEM_BYTES ((2 * 128 * 36 + 2 * 32 * 72) * 4)

template <bool GELU, bool RES>
__device__ __forceinline__ void gemm_body(
    const float* __restrict__ A, const float* __restrict__ W,
    const float* __restrict__ bias, float* __restrict__ C,
    int K, int M)
{
    extern __shared__ __align__(16) uint32_t dynsmem[];
    uint32_t* As = dynsmem;                 // [2][128*36]
    uint32_t* Ws = dynsmem + 2 * 128 * 36;  // [2][32*72]

    const int tid  = threadIdx.x;
    const int lane = tid & 31;
    const int wid  = tid >> 5;
    const int warp_m = wid >> 1;            // 0..1
    const int warp_n = wid & 1;             // 0..1
    const int r0   = lane >> 2;
    const int quad = lane & 3;
    const int row0 = blockIdx.y * 128;
    const int col0 = blockIdx.x * 64;

    // ldmatrix A address pattern: row = rb + (lane&15), col-word = kk + ((lane>>4)<<2)
    const int lm_row = lane & 15;
    const int lm_col = (lane >> 4) << 2;

    float acc[4][4][4] = {};

    auto load_stage = [&](int k0, int s) {
        const float* Ab = A + (size_t)row0 * K + k0;
        uint32_t* Asb = As + s * (128 * 36);
        #pragma unroll
        for (int i = 0; i < 8; i++) {
            int e = tid + i * 128;
            int r = e >> 3, c4 = e & 7;
            CPA16(smem_u32(&Asb[r * 36 + c4 * 4]), Ab + (size_t)r * K + c4 * 4);
        }
        const float* Wb = W + (size_t)k0 * M + col0;
        uint32_t* Wsb = Ws + s * (32 * 72);
        #pragma unroll
        for (int i = 0; i < 4; i++) {
            int e = tid + i * 128;
            int r = e >> 4, c4 = e & 15;
            CPA16(smem_u32(&Wsb[r * 72 + c4 * 4]), Wb + (size_t)r * M + c4 * 4);
        }
        CPA_COMMIT();
    };

    load_stage(0, 0);
    const int nk = K >> 5;

    for (int it = 0; it < nk; ++it) {
        const int s = it & 1;
        if (it + 1 < nk) { load_stage((it + 1) * 32, s ^ 1); CPA_WAIT1(); }
        else             { CPA_WAIT0(); }
        __syncthreads();

        const uint32_t* Asb = As + s * (128 * 36);
        const uint32_t* Wsb = Ws + s * (32 * 72);

        #pragma unroll
        for (int ks = 0; ks < 4; ks++) {
            const int kk = ks * 8;
            uint32_t a[4][4], b[4][2];
            #pragma unroll
            for (int mi = 0; mi < 4; mi++) {
                const int rb = warp_m * 64 + mi * 16;
                ldsm4(a[mi], smem_u32(&Asb[(rb + lm_row) * 36 + kk + lm_col]));
            }
            #pragma unroll
            for (int ni = 0; ni < 4; ni++) {
                const int cb = warp_n * 32 + ni * 8 + r0;
                b[ni][0] = Wsb[(kk + quad) * 72 + cb];
                b[ni][1] = Wsb[(kk + 4 + quad) * 72 + cb];
            }
            #pragma unroll
            for (int mi = 0; mi < 4; mi++)
                #pragma unroll
                for (int ni = 0; ni < 4; ni++)
                    mma_tf32(acc[mi][ni], a[mi], b[ni]);
        }
        __syncthreads();
    }

    #pragma unroll
    for (int mi = 0; mi < 4; mi++) {
        #pragma unroll
        for (int ni = 0; ni < 4; ni++) {
            const int r = row0 + warp_m * 64 + mi * 16 + r0;
            const int c = col0 + warp_n * 32 + ni * 8 + 2 * quad;
            const float bx = bias[c], by = bias[c + 1];
            float v0 = acc[mi][ni][0] + bx;
            float v1 = acc[mi][ni][1] + by;
            float v2 = acc[mi][ni][2] + bx;
            float v3 = acc[mi][ni][3] + by;
            if (GELU) {
                v0 = 0.5f * v0 * (1.0f + erff(v0 * 0.70710678118654752f));
                v1 = 0.5f * v1 * (1.0f + erff(v1 * 0.70710678118654752f));
                v2 = 0.5f * v2 * (1.0f + erff(v2 * 0.70710678118654752f));
                v3 = 0.5f * v3 * (1.0f + erff(v3 * 0.70710678118654752f));
            }
            if (RES) {
                float2 e0 = *reinterpret_cast<const float2*>(&C[(size_t)r * M + c]);
                float2 e1 = *reinterpret_cast<const float2*>(&C[(size_t)(r + 8) * M + c]);
                v0 += e0.x; v1 += e0.y; v2 += e1.x; v3 += e1.y;
            }
            *reinterpret_cast<float2*>(&C[(size_t)r * M + c])       = make_float2(v0, v1);
            *reinterpret_cast<float2*>(&C[(size_t)(r + 8) * M + c]) = make_float2(v2, v3);
        }
    }
}

template <bool GELU, bool RES>
__global__ void __launch_bounds__(128) gemm_kernel(
    const float* __restrict__ A, const float* __restrict__ W,
    const float* __restrict__ bias, float* __restrict__ C, int K, int M)
{
    gemm_body<GELU, RES>(A, W, bias, C, K, M);
}

__global__ void __launch_bounds__(128) qkv_kernel(
    const float* __restrict__ A,
    const float* __restrict__ wq, const float* __restrict__ wk, const float* __restrict__ wv,
    const float* __restrict__ bq, const float* __restrict__ bk, const float* __restrict__ bv,
    float* __restrict__ q, float* __restrict__ k, float* __restrict__ v)
{
    const float* W; const float* B; float* C;
    if (blockIdx.z == 0)      { W = wq; B = bq; C = q; }
    else if (blockIdx.z == 1) { W = wk; B = bk; C = k; }
    else                      { W = wv; B = bv; C = v; }
    gemm_body<false, false>(A, W, B, C, D_MODEL, D_MODEL);
}

// ---------------------------------------------------------------------------
// Flash attention: CTA = 128 queries (4 warps x 32q), KV tiles of 64, 2-stage.
// Q frags hoisted to registers; K/P frags via ldmatrix; V scalar LDS.
// smem: Qs[128*36] Ks[2][64*36] Vs[2][64*40] Ps[128*68] = 92160 B
// ---------------------------------------------------------------------------
#define ATTN_SMEM_BYTES ((128 * 36 + 2 * 64 * 36 + 2 * 64 * 40 + 128 * 68) * 4)

__global__ void __launch_bounds__(128) attn_kernel(
    const float* __restrict__ Q, const float* __restrict__ K,
    const float* __restrict__ V, float* __restrict__ O)
{
    extern __shared__ __align__(16) uint32_t dyn[];
    uint32_t* Qs = dyn;                      // 128*36
    uint32_t* Ks = Qs + 128 * 36;            // [2][64*36]
    uint32_t* Vs = Ks + 2 * 64 * 36;         // [2][64*40]
    uint32_t* Ps = Vs + 2 * 64 * 40;         // 128*68

    const int tid  = threadIdx.x;
    const int lane = tid & 31;
    const int w    = tid >> 5;
    const int r0   = lane >> 2;
    const int quad = lane & 3;
    const int q0   = blockIdx.x * 128;
    const int h    = blockIdx.y;
    const int b    = blockIdx.z;
    const float scale = 0.17677669529663687f;  // 1/sqrt(32)
    const int base = (b * SEQ) * D_MODEL + h * HEAD_DIM;

    // ldmatrix patterns
    const int lm_row = lane & 15;
    const int lm_col = (lane >> 4) << 2;
    const int lmb_row = (lane & 7) + ((lane >> 4) << 3);   // B-frag x4: rows
    const int lmb_col = ((lane >> 3) & 1) << 2;            // B-frag x4: col word

    auto load_kv = [&](int kt, int s) {
        uint32_t* Ksb = Ks + s * (64 * 36);
        uint32_t* Vsb = Vs + s * (64 * 40);
        #pragma unroll
        for (int i = 0; i < 4; i++) {
            const int r = (tid >> 3) + i * 16;
            const int c4 = tid & 7;
            CPA16(smem_u32(&Ksb[r * 36 + c4 * 4]), &K[base + (kt + r) * D_MODEL + c4 * 4]);
            CPA16(smem_u32(&Vsb[r * 40 + c4 * 4]), &V[base + (kt + r) * D_MODEL + c4 * 4]);
        }
        CPA_COMMIT();
    };

    load_kv(0, 0);

    // Q tile -> smem (scaled), then hoist Q frags to registers
    #pragma unroll
    for (int i = 0; i < 8; i++) {
        int e = tid + i * 128;
        int r = e >> 3, c4 = e & 7;
        float4 v = *reinterpret_cast<const float4*>(&Q[base + (q0 + r) * D_MODEL + c4 * 4]);
        uint4 u = make_uint4(__float_as_uint(v.x * scale), __float_as_uint(v.y * scale),
                             __float_as_uint(v.z * scale), __float_as_uint(v.w * scale));
        *reinterpret_cast<uint4*>(&Qs[r * 36 + c4 * 4]) = u;
    }
    __syncthreads();

    uint32_t qf[2][4][4];   // [mi][ks][frag]
    #pragma unroll
    for (int mi = 0; mi < 2; mi++) {
        const int rb = w * 32 + mi * 16;
        #pragma unroll
        for (int ks = 0; ks < 4; ks++)
            ldsm4(qf[mi][ks], smem_u32(&Qs[(rb + lm_row) * 36 + ks * 8 + lm_col]));
    }

    float m[2][2], l[2][2], o[2][4][4] = {};
    #pragma unroll
    for (int mi = 0; mi < 2; mi++) { m[mi][0] = m[mi][1] = -1e30f; l[mi][0] = l[mi][1] = 0.f; }

    const int NIT = SEQ / 64;
    for (int it = 0; it < NIT; ++it) {
        const int s = it & 1;
        __syncthreads();
        if (it + 1 < NIT) { load_kv((it + 1) * 64, s ^ 1); CPA_WAIT1(); }
        else              { CPA_WAIT0(); }
        __syncthreads();

        const uint32_t* Ksb = Ks + s * (64 * 36);
        const uint32_t* Vsb = Vs + s * (64 * 40);

        // S = Q K^T : per warp 32x64
        float sc[2][8][4] = {};
        #pragma unroll
        for (int ks = 0; ks < 4; ks++) {
            const int kk = ks * 8;
            uint32_t bfr[4][4];   // 4 ldsm.x4 -> 8 ni's worth of (b0,b1)
            #pragma unroll
            for (int nq = 0; nq < 4; nq++) {
                // covers ni = 2*nq, 2*nq+1
                ldsm4(bfr[nq], smem_u32(&Ksb[(nq * 16 + lmb_row) * 36 + kk + lmb_col]));
            }
            #pragma unroll
            for (int mi = 0; mi < 2; mi++) {
                #pragma unroll
                for (int nq = 0; nq < 4; nq++) {
                    mma_tf32(sc[mi][2 * nq],     qf[mi][ks], &bfr[nq][0]);
                    mma_tf32(sc[mi][2 * nq + 1], qf[mi][ks], &bfr[nq][2]);
                }
            }
        }

        // Online softmax, P -> smem
        #pragma unroll
        for (int mi = 0; mi < 2; mi++) {
            const int rb = w * 32 + mi * 16 + r0;
            float mt0 = -1e30f, mt1 = -1e30f;
            #pragma unroll
            for (int ni = 0; ni < 8; ni++) {
                mt0 = fmaxf(mt0, fmaxf(sc[mi][ni][0], sc[mi][ni][1]));
                mt1 = fmaxf(mt1, fmaxf(sc[mi][ni][2], sc[mi][ni][3]));
            }
            #pragma unroll
            for (int off = 1; off < 4; off <<= 1) {
                mt0 = fmaxf(mt0, __shfl_xor_sync(0xffffffffu, mt0, off));
                mt1 = fmaxf(mt1, __shfl_xor_sync(0xffffffffu, mt1, off));
            }
            const float mn0 = fmaxf(m[mi][0], mt0);
            const float mn1 = fmaxf(m[mi][1], mt1);
            const float alpha0 = __expf(m[mi][0] - mn0);
            const float alpha1 = __expf(m[mi][1] - mn1);
            m[mi][0] = mn0; m[mi][1] = mn1;

            float rs0 = 0.f, rs1 = 0.f;
            #pragma unroll
            for (int ni = 0; ni < 8; ni++) {
                const float p00 = __expf(sc[mi][ni][0] - mn0);
                const float p01 = __expf(sc[mi][ni][1] - mn0);
                const float p10 = __expf(sc[mi][ni][2] - mn1);
                const float p11 = __expf(sc[mi][ni][3] - mn1);
                rs0 += p00 + p01;
                rs1 += p10 + p11;
                const int col = ni * 8 + 2 * quad;
                *reinterpret_cast<float2*>(&Ps[rb * 68 + col]) = make_float2(p00, p01);
                *reinterpret_cast<float2*>(&Ps[(rb + 8) * 68 + col]) = make_float2(p10, p11);
            }
            #pragma unroll
            for (int off = 1; off < 4; off <<= 1) {
                rs0 += __shfl_xor_sync(0xffffffffu, rs0, off);
                rs1 += __shfl_xor_sync(0xffffffffu, rs1, off);
            }
            l[mi][0] = l[mi][0] * alpha0 + rs0;
            l[mi][1] = l[mi][1] * alpha1 + rs1;
            #pragma unroll
            for (int ni = 0; ni < 4; ni++) {
                o[mi][ni][0] *= alpha0; o[mi][ni][1] *= alpha0;
                o[mi][ni][2] *= alpha1; o[mi][ni][3] *= alpha1;
            }
        }
        __syncwarp();   // Ps rows are warp-private: order write -> ldmatrix read

        // O += P @ V
        #pragma unroll
        for (int ks = 0; ks < 8; ks++) {
            const int kk = ks * 8;
            uint32_t a[2][4];
            #pragma unroll
            for (int mi = 0; mi < 2; mi++) {
                const int rb = w * 32 + mi * 16;
                ldsm4(a[mi], smem_u32(&Ps[(rb + lm_row) * 68 + kk + lm_col]));
            }
            #pragma unroll
            for (int ni = 0; ni < 4; ni++) {
                uint32_t bb[2];
                const int nb = ni * 8 + r0;
                bb[0] = Vsb[(kk + quad) * 40 + nb];
                bb[1] = Vsb[(kk + 4 + quad) * 40 + nb];
                #pragma unroll
                for (int mi = 0; mi < 2; mi++)
                    mma_tf32(o[mi][ni], a[mi], bb);
            }
        }
    }

    #pragma unroll
    for (int mi = 0; mi < 2; mi++) {
        const float inv0 = 1.0f / l[mi][0];
        const float inv1 = 1.0f / l[mi][1];
        const int q = q0 + w * 32 + mi * 16 + r0;
        #pragma unroll
        for (int ni = 0; ni < 4; ni++) {
            const int d = ni * 8 + 2 * quad;
            *reinterpret_cast<float2*>(&O[base + q * D_MODEL + d]) =
                make_float2(o[mi][ni][0] * inv0, o[mi][ni][1] * inv0);
            *reinterpret_cast<float2*>(&O[base + (q + 8) * D_MODEL + d]) =
                make_float2(o[mi][ni][2] * inv1, o[mi][ni][3] * inv1);
        }
    }
}

// ---------------------------------------------------------------------------
// Launch
// ---------------------------------------------------------------------------
extern "C" void kernel_launch(void* const* d_in, const int* in_sizes, int n_in,
                              void* d_out, int out_size)
{
    const float* x    = (const float*)d_in[0];
    const float* ln1s = (const float*)d_in[1];
    const float* ln1b = (const float*)d_in[2];
    const float* wq   = (const float*)d_in[3];
    const float* bq   = (const float*)d_in[4];
    const float* wk   = (const float*)d_in[5];
    const float* bk   = (const float*)d_in[6];
    const float* wv   = (const float*)d_in[7];
    const float* bv   = (const float*)d_in[8];
    const float* wo   = (const float*)d_in[9];
    const float* bo   = (const float*)d_in[10];
    const float* ln2s = (const float*)d_in[11];
    const float* ln2b = (const float*)d_in[12];
    const float* w1   = (const float*)d_in[13];
    const float* b1   = (const float*)d_in[14];
    const float* w2   = (const float*)d_in[15];
    const float* b2   = (const float*)d_in[16];

    float* X = (float*)d_out;

    float *normed, *q, *k, *v, *attn, *ffh;
    cudaGetSymbolAddress((void**)&normed, g_normed);
    cudaGetSymbolAddress((void**)&q,      g_q);
    cudaGetSymbolAddress((void**)&k,      g_k);
    cudaGetSymbolAddress((void**)&v,      g_v);
    cudaGetSymbolAddress((void**)&attn,   g_attn);
    cudaGetSymbolAddress((void**)&ffh,    g_ffh);

    cudaFuncSetAttribute(gemm_kernel<false, true>,
                         cudaFuncAttributeMaxDynamicSharedMemorySize, GEMM_SMEM_BYTES);
    cudaFuncSetAttribute(gemm_kernel<true, false>,
                         cudaFuncAttributeMaxDynamicSharedMemorySize, GEMM_SMEM_BYTES);
    cudaFuncSetAttribute(qkv_kernel,
                         cudaFuncAttributeMaxDynamicSharedMemorySize, GEMM_SMEM_BYTES);
    cudaFuncSetAttribute(attn_kernel,
                         cudaFuncAttributeMaxDynamicSharedMemorySize, ATTN_SMEM_BYTES);

    cudaMemcpyAsync(X, x, (size_t)NTOK * D_MODEL * sizeof(float),
                    cudaMemcpyDeviceToDevice);

    const dim3 gemm_dd(D_MODEL / 64, NTOK / 128);     // (4, 64)
    const dim3 gemm_df(D_FF / 64,    NTOK / 128);     // (16, 64)
    const dim3 qkv_grid(D_MODEL / 64, NTOK / 128, 3); // (4, 64, 3)
    const dim3 attn_grid(SEQ / 128, N_HEADS, BATCH);  // (16, 8, 4)

    for (int l = 0; l < N_LAYERS; l++) {
        const int wdd = l * D_MODEL * D_MODEL;
        ln_kernel<<<NTOK, 256>>>(X, ln1s + l * D_MODEL, ln1b + l * D_MODEL, normed);

        qkv_kernel<<<qkv_grid, 128, GEMM_SMEM_BYTES>>>(normed,
                                      wq + wdd, wk + wdd, wv + wdd,
                                      bq + l * D_MODEL, bk + l * D_MODEL, bv + l * D_MODEL,
                                      q, k, v);

        attn_kernel<<<attn_grid, 128, ATTN_SMEM_BYTES>>>(q, k, v, attn);

        gemm_kernel<false, true><<<gemm_dd, 128, GEMM_SMEM_BYTES>>>(
            attn, wo + wdd, bo + l * D_MODEL, X, D_MODEL, D_MODEL);

        ln_kernel<<<NTOK, 256>>>(X, ln2s + l * D_MODEL, ln2b + l * D_MODEL, normed);

        gemm_kernel<true, false><<<gemm_df, 128, GEMM_SMEM_BYTES>>>(
            normed, w1 + l * D_MODEL * D_FF, b1 + l * D_FF, ffh, D_MODEL, D_FF);
        gemm_kernel<false, true><<<gemm_dd, 128, GEMM_SMEM_BYTES>>>(
            ffh, w2 + l * D_FF * D_MODEL, b2 + l * D_MODEL, X, D_FF, D_MODEL);
    }
}

// round 5
// speedup vs baseline: 3.5827x; 1.0397x over previous
#include <cuda_runtime.h>
#include <math.h>
#include <stdint.h>

#define D_MODEL   256
#define N_LAYERS  6
#define N_HEADS   8
#define D_FF      1024
#define HEAD_DIM  32
#define BATCH     4
#define SEQ       2048
#define NTOK      (BATCH * SEQ)   // 8192

// ---------------------------------------------------------------------------
// Scratch
// ---------------------------------------------------------------------------
__device__ float g_normed[NTOK * D_MODEL];
__device__ float g_q[NTOK * D_MODEL];
__device__ float g_k[NTOK * D_MODEL];
__device__ float g_v[NTOK * D_MODEL];
__device__ float g_attn[NTOK * D_MODEL];
__device__ float g_ffh[NTOK * D_FF];

// ---------------------------------------------------------------------------
// Helpers
// ---------------------------------------------------------------------------
__device__ __forceinline__ uint32_t smem_u32(const void* p) {
    return (uint32_t)__cvta_generic_to_shared(p);
}
#define CPA16(dst_u32, src_ptr) \
    asm volatile("cp.async.cg.shared.global [%0], [%1], 16;\n" :: "r"(dst_u32), "l"(src_ptr))
#define CPA_COMMIT() asm volatile("cp.async.commit_group;\n" ::)
#define CPA_WAIT2()  asm volatile("cp.async.wait_group 2;\n" ::)
#define CPA_WAIT1()  asm volatile("cp.async.wait_group 1;\n" ::)
#define CPA_WAIT0()  asm volatile("cp.async.wait_group 0;\n" ::)

__device__ __forceinline__ void mma_tf32(float* c, const uint32_t* a, const uint32_t* b) {
    asm volatile(
        "mma.sync.aligned.m16n8k8.row.col.f32.tf32.tf32.f32 "
        "{%0,%1,%2,%3},{%4,%5,%6,%7},{%8,%9},{%0,%1,%2,%3};\n"
        : "+f"(c[0]), "+f"(c[1]), "+f"(c[2]), "+f"(c[3])
        : "r"(a[0]), "r"(a[1]), "r"(a[2]), "r"(a[3]),
          "r"(b[0]), "r"(b[1]));
}

__device__ __forceinline__ void ldsm4(uint32_t* r, uint32_t byte_addr) {
    asm volatile("ldmatrix.sync.aligned.m8n8.x4.shared.b16 {%0,%1,%2,%3}, [%4];\n"
        : "=r"(r[0]), "=r"(r[1]), "=r"(r[2]), "=r"(r[3]) : "r"(byte_addr));
}

__device__ __forceinline__ float ex2(float x) {
    float y;
    asm("ex2.approx.f32 %0, %1;" : "=f"(y) : "f"(x));
    return y;
}

// ---------------------------------------------------------------------------
// LayerNorm
// ---------------------------------------------------------------------------
__global__ void __launch_bounds__(256) ln_kernel(
    const float* __restrict__ X, const float* __restrict__ S,
    const float* __restrict__ Bb, float* __restrict__ Y)
{
    const int row = blockIdx.x;
    const int tid = threadIdx.x;
    const float v = X[row * D_MODEL + tid];

    __shared__ float red[16];
    float s1 = v, s2 = v * v;
    #pragma unroll
    for (int off = 16; off > 0; off >>= 1) {
        s1 += __shfl_xor_sync(0xffffffffu, s1, off);
        s2 += __shfl_xor_sync(0xffffffffu, s2, off);
    }
    const int w = tid >> 5;
    if ((tid & 31) == 0) { red[w] = s1; red[8 + w] = s2; }
    __syncthreads();
    float sum = 0.f, sq = 0.f;
    #pragma unroll
    for (int i = 0; i < 8; i++) { sum += red[i]; sq += red[8 + i]; }
    const float mu  = sum * (1.0f / D_MODEL);
    const float var = sq * (1.0f / D_MODEL) - mu * mu;
    const float inv = rsqrtf(var + 1e-5f);
    Y[row * D_MODEL + tid] = (v - mu) * inv * S[tid] + Bb[tid];
}

// ---------------------------------------------------------------------------
// tf32 GEMM: block 64x64, BK=32, 128 threads (4 warps as 2m x 2n, 32x32/warp)
// A-frags via ldmatrix.x4, W-frags scalar LDS, 3-stage cp.async pipeline.
// smem: 3 * (64*36 + 32*72) * 4 = 55296 B -> 4 CTA/SM
// ---------------------------------------------------------------------------
#define GEMM_SMEM_BYTES (3 * (64 * 36 + 32 * 72) * 4)

template <bool GELU, bool RES>
__device__ __forceinline__ void gemm_body(
    const float* __restrict__ A, const float* __restrict__ W,
    const float* __restrict__ bias, float* __restrict__ C,
    int K, int M)
{
    extern __shared__ __align__(16) uint32_t dynsmem[];
    uint32_t* As = dynsmem;                 // [3][64*36]
    uint32_t* Ws = dynsmem + 3 * 64 * 36;   // [3][32*72]

    const int tid  = threadIdx.x;
    const int lane = tid & 31;
    const int wid  = tid >> 5;
    const int warp_m = wid >> 1;            // 0..1
    const int warp_n = wid & 1;             // 0..1
    const int r0   = lane >> 2;
    const int quad = lane & 3;
    const int row0 = blockIdx.y * 64;
    const int col0 = blockIdx.x * 64;

    const int lm_row = lane & 15;
    const int lm_col = (lane >> 4) << 2;

    float acc[2][4][4] = {};

    auto load_stage = [&](int k0, int s) {
        const float* Ab = A + (size_t)row0 * K + k0;
        uint32_t* Asb = As + s * (64 * 36);
        #pragma unroll
        for (int i = 0; i < 4; i++) {
            int r = (tid >> 3) + i * 16;     // 0..63
            int c4 = tid & 7;
            CPA16(smem_u32(&Asb[r * 36 + c4 * 4]), Ab + (size_t)r * K + c4 * 4);
        }
        const float* Wb = W + (size_t)k0 * M + col0;
        uint32_t* Wsb = Ws + s * (32 * 72);
        #pragma unroll
        for (int i = 0; i < 4; i++) {
            int r = (tid >> 4) + i * 8;      // 0..31
            int c4 = tid & 15;
            CPA16(smem_u32(&Wsb[r * 72 + c4 * 4]), Wb + (size_t)r * M + c4 * 4);
        }
        CPA_COMMIT();
    };

    const int nk = K >> 5;
    load_stage(0, 0);
    load_stage(32, 1);

    for (int it = 0; it < nk; ++it) {
        const int s = it % 3;
        if (it + 2 < nk)      { load_stage((it + 2) * 32, (it + 2) % 3); CPA_WAIT2(); }
        else if (it + 1 < nk) { CPA_WAIT1(); }
        else                  { CPA_WAIT0(); }
        __syncthreads();

        const uint32_t* Asb = As + s * (64 * 36);
        const uint32_t* Wsb = Ws + s * (32 * 72);

        #pragma unroll
        for (int ks = 0; ks < 4; ks++) {
            const int kk = ks * 8;
            uint32_t a[2][4], b[4][2];
            #pragma unroll
            for (int mi = 0; mi < 2; mi++) {
                const int rb = warp_m * 32 + mi * 16;
                ldsm4(a[mi], smem_u32(&Asb[(rb + lm_row) * 36 + kk + lm_col]));
            }
            #pragma unroll
            for (int ni = 0; ni < 4; ni++) {
                const int cb = warp_n * 32 + ni * 8 + r0;
                b[ni][0] = Wsb[(kk + quad) * 72 + cb];
                b[ni][1] = Wsb[(kk + 4 + quad) * 72 + cb];
            }
            #pragma unroll
            for (int mi = 0; mi < 2; mi++)
                #pragma unroll
                for (int ni = 0; ni < 4; ni++)
                    mma_tf32(acc[mi][ni], a[mi], b[ni]);
        }
        __syncthreads();
    }

    #pragma unroll
    for (int mi = 0; mi < 2; mi++) {
        #pragma unroll
        for (int ni = 0; ni < 4; ni++) {
            const int r = row0 + warp_m * 32 + mi * 16 + r0;
            const int c = col0 + warp_n * 32 + ni * 8 + 2 * quad;
            const float bx = bias[c], by = bias[c + 1];
            float v0 = acc[mi][ni][0] + bx;
            float v1 = acc[mi][ni][1] + by;
            float v2 = acc[mi][ni][2] + bx;
            float v3 = acc[mi][ni][3] + by;
            if (GELU) {
                v0 = 0.5f * v0 * (1.0f + erff(v0 * 0.70710678118654752f));
                v1 = 0.5f * v1 * (1.0f + erff(v1 * 0.70710678118654752f));
                v2 = 0.5f * v2 * (1.0f + erff(v2 * 0.70710678118654752f));
                v3 = 0.5f * v3 * (1.0f + erff(v3 * 0.70710678118654752f));
            }
            if (RES) {
                float2 e0 = *reinterpret_cast<const float2*>(&C[(size_t)r * M + c]);
                float2 e1 = *reinterpret_cast<const float2*>(&C[(size_t)(r + 8) * M + c]);
                v0 += e0.x; v1 += e0.y; v2 += e1.x; v3 += e1.y;
            }
            *reinterpret_cast<float2*>(&C[(size_t)r * M + c])       = make_float2(v0, v1);
            *reinterpret_cast<float2*>(&C[(size_t)(r + 8) * M + c]) = make_float2(v2, v3);
        }
    }
}

template <bool GELU, bool RES>
__global__ void __launch_bounds__(128) gemm_kernel(
    const float* __restrict__ A, const float* __restrict__ W,
    const float* __restrict__ bias, float* __restrict__ C, int K, int M)
{
    gemm_body<GELU, RES>(A, W, bias, C, K, M);
}

__global__ void __launch_bounds__(128) qkv_kernel(
    const float* __restrict__ A,
    const float* __restrict__ wq, const float* __restrict__ wk, const float* __restrict__ wv,
    const float* __restrict__ bq, const float* __restrict__ bk, const float* __restrict__ bv,
    float* __restrict__ q, float* __restrict__ k, float* __restrict__ v)
{
    const float* W; const float* B; float* C;
    if (blockIdx.z == 0)      { W = wq; B = bq; C = q; }
    else if (blockIdx.z == 1) { W = wk; B = bk; C = k; }
    else                      { W = wv; B = bv; C = v; }
    gemm_body<false, false>(A, W, B, C, D_MODEL, D_MODEL);
}

// ---------------------------------------------------------------------------
// Flash attention: CTA = 128 queries (4 warps x 32q), KV tiles of 64, 3-stage.
// Softmax in log2 domain (ex2.approx). Q frags in registers, K/P via ldmatrix.
// smem: Qs[128*36] + 3*(Ks[64*36]+Vs[64*40]) + Ps[128*68] = 111616 B
// ---------------------------------------------------------------------------
#define ATTN_SMEM_BYTES ((128 * 36 + 3 * (64 * 36 + 64 * 40) + 128 * 68) * 4)

__global__ void __launch_bounds__(128) attn_kernel(
    const float* __restrict__ Q, const float* __restrict__ K,
    const float* __restrict__ V, float* __restrict__ O)
{
    extern __shared__ __align__(16) uint32_t dyn[];
    uint32_t* Qs = dyn;                      // 128*36
    uint32_t* Ks = Qs + 128 * 36;            // [3][64*36]
    uint32_t* Vs = Ks + 3 * 64 * 36;         // [3][64*40]
    uint32_t* Ps = Vs + 3 * 64 * 40;         // 128*68

    const int tid  = threadIdx.x;
    const int lane = tid & 31;
    const int w    = tid >> 5;
    const int r0   = lane >> 2;
    const int quad = lane & 3;
    const int q0   = blockIdx.x * 128;
    const int h    = blockIdx.y;
    const int b    = blockIdx.z;
    // 1/sqrt(32) * log2(e): softmax computed in base-2 domain
    const float scale2 = 0.17677669529663687f * 1.4426950408889634f;
    const int base = (b * SEQ) * D_MODEL + h * HEAD_DIM;

    const int lm_row = lane & 15;
    const int lm_col = (lane >> 4) << 2;
    const int lmb_row = (lane & 7) + ((lane >> 4) << 3);
    const int lmb_col = ((lane >> 3) & 1) << 2;

    auto load_kv = [&](int kt, int s) {
        uint32_t* Ksb = Ks + s * (64 * 36);
        uint32_t* Vsb = Vs + s * (64 * 40);
        #pragma unroll
        for (int i = 0; i < 4; i++) {
            const int r = (tid >> 3) + i * 16;
            const int c4 = tid & 7;
            CPA16(smem_u32(&Ksb[r * 36 + c4 * 4]), &K[base + (kt + r) * D_MODEL + c4 * 4]);
            CPA16(smem_u32(&Vsb[r * 40 + c4 * 4]), &V[base + (kt + r) * D_MODEL + c4 * 4]);
        }
        CPA_COMMIT();
    };

    load_kv(0, 0);
    load_kv(64, 1);

    // Q tile -> smem (scaled to log2 domain), then hoist Q frags to registers
    #pragma unroll
    for (int i = 0; i < 8; i++) {
        int e = tid + i * 128;
        int r = e >> 3, c4 = e & 7;
        float4 v = *reinterpret_cast<const float4*>(&Q[base + (q0 + r) * D_MODEL + c4 * 4]);
        uint4 u = make_uint4(__float_as_uint(v.x * scale2), __float_as_uint(v.y * scale2),
                             __float_as_uint(v.z * scale2), __float_as_uint(v.w * scale2));
        *reinterpret_cast<uint4*>(&Qs[r * 36 + c4 * 4]) = u;
    }
    __syncthreads();

    uint32_t qf[2][4][4];
    #pragma unroll
    for (int mi = 0; mi < 2; mi++) {
        const int rb = w * 32 + mi * 16;
        #pragma unroll
        for (int ks = 0; ks < 4; ks++)
            ldsm4(qf[mi][ks], smem_u32(&Qs[(rb + lm_row) * 36 + ks * 8 + lm_col]));
    }

    float m[2][2], l[2][2], o[2][4][4] = {};
    #pragma unroll
    for (int mi = 0; mi < 2; mi++) { m[mi][0] = m[mi][1] = -1e30f; l[mi][0] = l[mi][1] = 0.f; }

    const int NIT = SEQ / 64;
    for (int it = 0; it < NIT; ++it) {
        const int s = it % 3;
        if (it + 2 < NIT)      { load_kv((it + 2) * 64, (it + 2) % 3); CPA_WAIT2(); }
        else if (it + 1 < NIT) { CPA_WAIT1(); }
        else                   { CPA_WAIT0(); }
        __syncthreads();

        const uint32_t* Ksb = Ks + s * (64 * 36);
        const uint32_t* Vsb = Vs + s * (64 * 40);

        // S = Q K^T (log2-scaled)
        float sc[2][8][4] = {};
        #pragma unroll
        for (int ks = 0; ks < 4; ks++) {
            const int kk = ks * 8;
            uint32_t bfr[4][4];
            #pragma unroll
            for (int nq = 0; nq < 4; nq++)
                ldsm4(bfr[nq], smem_u32(&Ksb[(nq * 16 + lmb_row) * 36 + kk + lmb_col]));
            #pragma unroll
            for (int mi = 0; mi < 2; mi++) {
                #pragma unroll
                for (int nq = 0; nq < 4; nq++) {
                    mma_tf32(sc[mi][2 * nq],     qf[mi][ks], &bfr[nq][0]);
                    mma_tf32(sc[mi][2 * nq + 1], qf[mi][ks], &bfr[nq][2]);
                }
            }
        }

        // Online softmax (base-2), P -> smem
        #pragma unroll
        for (int mi = 0; mi < 2; mi++) {
            const int rb = w * 32 + mi * 16 + r0;
            float mt0 = -1e30f, mt1 = -1e30f;
            #pragma unroll
            for (int ni = 0; ni < 8; ni++) {
                mt0 = fmaxf(mt0, fmaxf(sc[mi][ni][0], sc[mi][ni][1]));
                mt1 = fmaxf(mt1, fmaxf(sc[mi][ni][2], sc[mi][ni][3]));
            }
            #pragma unroll
            for (int off = 1; off < 4; off <<= 1) {
                mt0 = fmaxf(mt0, __shfl_xor_sync(0xffffffffu, mt0, off));
                mt1 = fmaxf(mt1, __shfl_xor_sync(0xffffffffu, mt1, off));
            }
            const float mn0 = fmaxf(m[mi][0], mt0);
            const float mn1 = fmaxf(m[mi][1], mt1);
            const float alpha0 = ex2(m[mi][0] - mn0);
            const float alpha1 = ex2(m[mi][1] - mn1);
            m[mi][0] = mn0; m[mi][1] = mn1;

            float rs0 = 0.f, rs1 = 0.f;
            #pragma unroll
            for (int ni = 0; ni < 8; ni++) {
                const float p00 = ex2(sc[mi][ni][0] - mn0);
                const float p01 = ex2(sc[mi][ni][1] - mn0);
                const float p10 = ex2(sc[mi][ni][2] - mn1);
                const float p11 = ex2(sc[mi][ni][3] - mn1);
                rs0 += p00 + p01;
                rs1 += p10 + p11;
                const int col = ni * 8 + 2 * quad;
                *reinterpret_cast<float2*>(&Ps[rb * 68 + col]) = make_float2(p00, p01);
                *reinterpret_cast<float2*>(&Ps[(rb + 8) * 68 + col]) = make_float2(p10, p11);
            }
            #pragma unroll
            for (int off = 1; off < 4; off <<= 1) {
                rs0 += __shfl_xor_sync(0xffffffffu, rs0, off);
                rs1 += __shfl_xor_sync(0xffffffffu, rs1, off);
            }
            l[mi][0] = l[mi][0] * alpha0 + rs0;
            l[mi][1] = l[mi][1] * alpha1 + rs1;
            #pragma unroll
            for (int ni = 0; ni < 4; ni++) {
                o[mi][ni][0] *= alpha0; o[mi][ni][1] *= alpha0;
                o[mi][ni][2] *= alpha1; o[mi][ni][3] *= alpha1;
            }
        }
        __syncwarp();

        // O += P @ V
        #pragma unroll
        for (int ks = 0; ks < 8; ks++) {
            const int kk = ks * 8;
            uint32_t a[2][4];
            #pragma unroll
            for (int mi = 0; mi < 2; mi++) {
                const int rb = w * 32 + mi * 16;
                ldsm4(a[mi], smem_u32(&Ps[(rb + lm_row) * 68 + kk + lm_col]));
            }
            #pragma unroll
            for (int ni = 0; ni < 4; ni++) {
                uint32_t bb[2];
                const int nb = ni * 8 + r0;
                bb[0] = Vsb[(kk + quad) * 40 + nb];
                bb[1] = Vsb[(kk + 4 + quad) * 40 + nb];
                #pragma unroll
                for (int mi = 0; mi < 2; mi++)
                    mma_tf32(o[mi][ni], a[mi], bb);
            }
        }
        __syncthreads();   // all warps done with stage s before it+1 overwrites it
    }

    #pragma unroll
    for (int mi = 0; mi < 2; mi++) {
        const float inv0 = 1.0f / l[mi][0];
        const float inv1 = 1.0f / l[mi][1];
        const int q = q0 + w * 32 + mi * 16 + r0;
        #pragma unroll
        for (int ni = 0; ni < 4; ni++) {
            const int d = ni * 8 + 2 * quad;
            *reinterpret_cast<float2*>(&O[base + q * D_MODEL + d]) =
                make_float2(o[mi][ni][0] * inv0, o[mi][ni][1] * inv0);
            *reinterpret_cast<float2*>(&O[base + (q + 8) * D_MODEL + d]) =
                make_float2(o[mi][ni][2] * inv1, o[mi][ni][3] * inv1);
        }
    }
}

// ---------------------------------------------------------------------------
// Launch
// ---------------------------------------------------------------------------
extern "C" void kernel_launch(void* const* d_in, const int* in_sizes, int n_in,
                              void* d_out, int out_size)
{
    const float* x    = (const float*)d_in[0];
    const float* ln1s = (const float*)d_in[1];
    const float* ln1b = (const float*)d_in[2];
    const float* wq   = (const float*)d_in[3];
    const float* bq   = (const float*)d_in[4];
    const float* wk   = (const float*)d_in[5];
    const float* bk   = (const float*)d_in[6];
    const float* wv   = (const float*)d_in[7];
    const float* bv   = (const float*)d_in[8];
    const float* wo   = (const float*)d_in[9];
    const float* bo   = (const float*)d_in[10];
    const float* ln2s = (const float*)d_in[11];
    const float* ln2b = (const float*)d_in[12];
    const float* w1   = (const float*)d_in[13];
    const float* b1   = (const float*)d_in[14];
    const float* w2   = (const float*)d_in[15];
    const float* b2   = (const float*)d_in[16];

    float* X = (float*)d_out;

    float *normed, *q, *k, *v, *attn, *ffh;
    cudaGetSymbolAddress((void**)&normed, g_normed);
    cudaGetSymbolAddress((void**)&q,      g_q);
    cudaGetSymbolAddress((void**)&k,      g_k);
    cudaGetSymbolAddress((void**)&v,      g_v);
    cudaGetSymbolAddress((void**)&attn,   g_attn);
    cudaGetSymbolAddress((void**)&ffh,    g_ffh);

    cudaFuncSetAttribute(gemm_kernel<false, true>,
                         cudaFuncAttributeMaxDynamicSharedMemorySize, GEMM_SMEM_BYTES);
    cudaFuncSetAttribute(gemm_kernel<true, false>,
                         cudaFuncAttributeMaxDynamicSharedMemorySize, GEMM_SMEM_BYTES);
    cudaFuncSetAttribute(qkv_kernel,
                         cudaFuncAttributeMaxDynamicSharedMemorySize, GEMM_SMEM_BYTES);
    cudaFuncSetAttribute(attn_kernel,
                         cudaFuncAttributeMaxDynamicSharedMemorySize, ATTN_SMEM_BYTES);

    cudaMemcpyAsync(X, x, (size_t)NTOK * D_MODEL * sizeof(float),
                    cudaMemcpyDeviceToDevice);

    const dim3 gemm_dd(D_MODEL / 64, NTOK / 64);      // (4, 128) = 512
    const dim3 gemm_df(D_FF / 64,    NTOK / 64);      // (16, 128) = 2048
    const dim3 qkv_grid(D_MODEL / 64, NTOK / 64, 3);  // 1536
    const dim3 attn_grid(SEQ / 128, N_HEADS, BATCH);  // (16, 8, 4)

    for (int l = 0; l < N_LAYERS; l++) {
        const int wdd = l * D_MODEL * D_MODEL;
        ln_kernel<<<NTOK, 256>>>(X, ln1s + l * D_MODEL, ln1b + l * D_MODEL, normed);

        qkv_kernel<<<qkv_grid, 128, GEMM_SMEM_BYTES>>>(normed,
                                      wq + wdd, wk + wdd, wv + wdd,
                                      bq + l * D_MODEL, bk + l * D_MODEL, bv + l * D_MODEL,
                                      q, k, v);

        attn_kernel<<<attn_grid, 128, ATTN_SMEM_BYTES>>>(q, k, v, attn);

        gemm_kernel<false, true><<<gemm_dd, 128, GEMM_SMEM_BYTES>>>(
            attn, wo + wdd, bo + l * D_MODEL, X, D_MODEL, D_MODEL);

        ln_kernel<<<NTOK, 256>>>(X, ln2s + l * D_MODEL, ln2b + l * D_MODEL, normed);

        gemm_kernel<true, false><<<gemm_df, 128, GEMM_SMEM_BYTES>>>(
            normed, w1 + l * D_MODEL * D_FF, b1 + l * D_FF, ffh, D_MODEL, D_FF);
        gemm_kernel<false, true><<<gemm_dd, 128, GEMM_SMEM_BYTES>>>(
            ffh, w2 + l * D_FF * D_MODEL, b2 + l * D_MODEL, X, D_FF, D_MODEL);
    }
}